// round 13
// baseline (speedup 1.0000x reference)
#include <cuda_runtime.h>
#include <cuda_fp16.h>
#include <cstdint>

#define BATCH 4
#define CH    128
#define NTOK  4096
#define NPAD  4224   // NTOK + one pad tile
#define ASTR  136    // smem tile stride in halves

// ---- scratch (device globals; no runtime allocation) ----
__device__ __half g_Q [(size_t)BATCH * NTOK * CH];
__device__ __half g_Kc[(size_t)BATCH * NPAD * CH];   // compacted K (written by proj)
__device__ __half g_Vc[(size_t)BATCH * NPAD * CH];   // compacted V (written by proj)
__device__ int    g_scat[BATCH * NTOK];              // dest index for valid keys
__device__ int    g_nvalid[BATCH];

// ---- PTX helpers ----
__device__ __forceinline__ void mma16816(float* c,
    uint32_t a0, uint32_t a1, uint32_t a2, uint32_t a3,
    uint32_t b0, uint32_t b1)
{
    asm volatile(
        "mma.sync.aligned.m16n8k16.row.col.f32.f16.f16.f32 "
        "{%0,%1,%2,%3},{%4,%5,%6,%7},{%8,%9},{%0,%1,%2,%3};\n"
        : "+f"(c[0]), "+f"(c[1]), "+f"(c[2]), "+f"(c[3])
        : "r"(a0), "r"(a1), "r"(a2), "r"(a3), "r"(b0), "r"(b1));
}
__device__ __forceinline__ void ldsm_x4(uint32_t& r0, uint32_t& r1, uint32_t& r2, uint32_t& r3, uint32_t a)
{
    asm volatile("ldmatrix.sync.aligned.m8n8.x4.shared.b16 {%0,%1,%2,%3}, [%4];\n"
                 : "=r"(r0), "=r"(r1), "=r"(r2), "=r"(r3) : "r"(a));
}
__device__ __forceinline__ void ldsm_x4_t(uint32_t& r0, uint32_t& r1, uint32_t& r2, uint32_t& r3, uint32_t a)
{
    asm volatile("ldmatrix.sync.aligned.m8n8.x4.trans.shared.b16 {%0,%1,%2,%3}, [%4];\n"
                 : "=r"(r0), "=r"(r1), "=r"(r2), "=r"(r3) : "r"(a));
}
__device__ __forceinline__ float ex2f(float x)
{ float r; asm("ex2.approx.f32 %0, %1;" : "=f"(r) : "f"(x)); return r; }
__device__ __forceinline__ uint32_t pack_h2(float lo, float hi)
{ __half2 h = __floats2half2_rn(lo, hi); return *reinterpret_cast<uint32_t*>(&h); }
__device__ __forceinline__ void cp16(uint32_t d, const void* s)
{ asm volatile("cp.async.cg.shared.global [%0], [%1], 16;\n" :: "r"(d), "l"(s)); }

// ============================================================================
// Kernel S: per-batch mask scan -> scatter indices + nvalid + pad-tile zeroing
// grid = (4), 256 threads.  int4-vectorized mask reads.
// ============================================================================
__global__ __launch_bounds__(256, 1) void scan_kernel(const int* __restrict__ mask)
{
    __shared__ int ws[9];
    const int b = blockIdx.x, tid = threadIdx.x;
    const int lane = tid & 31, warp = tid >> 5;
    const int base = b * NTOK + tid * 16;

    int4 mv[4];
#pragma unroll
    for (int q = 0; q < 4; q++) mv[q] = *(const int4*)(mask + base + q * 4);
    int m[16]; int c = 0;
#pragma unroll
    for (int q = 0; q < 4; q++) {
        m[q * 4 + 0] = (mv[q].x > 0);
        m[q * 4 + 1] = (mv[q].y > 0);
        m[q * 4 + 2] = (mv[q].z > 0);
        m[q * 4 + 3] = (mv[q].w > 0);
    }
#pragma unroll
    for (int k = 0; k < 16; k++) c += m[k];
    int pre = c;
#pragma unroll
    for (int d = 1; d < 32; d <<= 1) {
        int n = __shfl_up_sync(0xffffffffu, pre, d);
        if (lane >= d) pre += n;
    }
    if (lane == 31) ws[warp] = pre;
    __syncthreads();
    if (tid == 0) {
        int s = 0;
#pragma unroll
        for (int w = 0; w < 8; w++) { int t = ws[w]; ws[w] = s; s += t; }
        ws[8] = s;
        g_nvalid[b] = s;
    }
    __syncthreads();
    int off = ws[warp] + pre - c;
#pragma unroll
    for (int k = 0; k < 16; k++) { if (m[k]) g_scat[base + k] = off++; }

    // zero-fill pad rows [nv, roundup128(nv)) — proj never writes these
    const int nv = ws[8];
    const int padEnd = ((nv + 127) >> 7) << 7;
    const uint4 z = make_uint4(0, 0, 0, 0);
    for (int i = nv * 16 + tid; i < padEnd * 16; i += 256) {
        *(uint4*)(g_Kc + (size_t)b * NPAD * CH + (size_t)i * 8) = z;
        *(uint4*)(g_Vc + (size_t)b * NPAD * CH + (size_t)i * 8) = z;
    }
}

// ============================================================================
// Kernel 1: QKV projections.  K/V rows scatter directly to compacted buffers.
// ============================================================================
__global__ __launch_bounds__(256, 1) void proj_kernel(
    const float* __restrict__ pf, const float* __restrict__ x,
    const float* __restrict__ Wq, const float* __restrict__ bq,
    const float* __restrict__ Wk, const float* __restrict__ bk,
    const float* __restrict__ Wv, const float* __restrict__ bv,
    const int* __restrict__ mask)
{
    extern __shared__ char sm[];
    __half* As  = (__half*)sm;
    __half* Ws  = (__half*)(sm + 128 * ASTR * 2);
    float*  bia = (float*)(sm + 2 * 128 * ASTR * 2);

    const int tid = threadIdx.x;
    const int p   = blockIdx.y;
    const float* src = (p == 0) ? pf : x;
    const float* W   = (p == 0) ? Wq : (p == 1 ? Wk : Wv);
    const float* bv_ = (p == 0) ? bq : (p == 1 ? bk : bv);
    const float oscale = (p == 0) ? (1.4426950408889634f / 11.313708498984761f) : 1.0f;

    const int t  = blockIdx.x;
    const int b  = t >> 5;
    const int n0 = (t & 31) * 128;

    for (int i = tid; i < 128 * 128; i += 256) {
        int c = i >> 7, tk = i & 127;
        As[tk * ASTR + c] = __float2half(src[((size_t)(b * CH + c)) * NTOK + n0 + tk]);
    }
    for (int i = tid; i < 128 * 128; i += 256) {
        int o = i >> 7, k = i & 127;
        Ws[o * ASTR + k] = __float2half(W[o * CH + k]);
    }
    if (tid < 128) bia[tid] = bv_[tid];
    __syncthreads();

    const int lane = tid & 31, warp = tid >> 5;
    const int g = lane >> 2, tg = lane & 3;
    const int wm = warp * 16;

    uint32_t qa[8][4];
#pragma unroll
    for (int ks = 0; ks < 8; ks++) {
        const __half* base = &As[(wm + g) * ASTR + ks * 16 + 2 * tg];
        qa[ks][0] = *(const uint32_t*)(base);
        qa[ks][1] = *(const uint32_t*)(base + 8 * ASTR);
        qa[ks][2] = *(const uint32_t*)(base + 8);
        qa[ks][3] = *(const uint32_t*)(base + 8 * ASTR + 8);
    }

    // destination rows for this thread's two output rows
    const int gi0 = b * NTOK + n0 + wm + g;
    const int gi1 = gi0 + 8;
    size_t row0, row1;
    bool st0 = true, st1 = true;
    __half* dst;
    if (p == 0) {
        dst = g_Q;
        row0 = (size_t)gi0 * CH;
        row1 = (size_t)gi1 * CH;
    } else {
        dst = (p == 1) ? g_Kc : g_Vc;
        st0 = (mask[gi0] > 0);
        st1 = (mask[gi1] > 0);
        row0 = st0 ? ((size_t)b * NPAD + g_scat[gi0]) * CH : 0;
        row1 = st1 ? ((size_t)b * NPAD + g_scat[gi1]) * CH : 0;
    }

#pragma unroll
    for (int nt = 0; nt < 16; nt++) {
        float acc[4] = {0.f, 0.f, 0.f, 0.f};
#pragma unroll
        for (int ks = 0; ks < 8; ks++) {
            const __half* kb = &Ws[(nt * 8 + g) * ASTR + ks * 16 + 2 * tg];
            uint32_t b0 = *(const uint32_t*)kb;
            uint32_t b1 = *(const uint32_t*)(kb + 8);
            mma16816(acc, qa[ks][0], qa[ks][1], qa[ks][2], qa[ks][3], b0, b1);
        }
        int col = nt * 8 + 2 * tg;
        float bb0 = bia[col], bb1 = bia[col + 1];
        if (st0)
            *(__half2*)&dst[row0 + col] =
                __floats2half2_rn((acc[0] + bb0) * oscale, (acc[1] + bb1) * oscale);
        if (st1)
            *(__half2*)&dst[row1 + col] =
                __floats2half2_rn((acc[2] + bb0) * oscale, (acc[3] + bb1) * oscale);
    }
}

// ============================================================================
// Kernel 2: flash attention over compacted keys + residual + LayerNorm.
// grid=(64 qtiles, 4 batch), 128 threads (4 warps x 16 queries), 2 CTAs/SM.
// smem: K0 0 | K1 34816 | V 69632   (104448 B)
// Epilogue: x staged through smem (Xs at V region) with coalesced float4 loads.
// ============================================================================
#define KOFF(i) ((i) * 34816)
#define VOFF    69632
#define SMATT   104448

__global__ __launch_bounds__(128, 2) void attn_kernel(
    const float* __restrict__ x,
    const float* __restrict__ gamma, const float* __restrict__ beta,
    float* __restrict__ out)
{
    extern __shared__ char sm[];
    const uint32_t sb = (uint32_t)__cvta_generic_to_shared(sm);
    float* Ot = (float*)sm;              // epilogue out staging [128 ch][68], overlaps K0
    float* Xs = (float*)(sm + VOFF);     // epilogue x staging [128 ch][68], overlaps V

    const int tid  = threadIdx.x;
    const int lane = tid & 31, warp = tid >> 5;
    const int g = lane >> 2, tg = lane & 3;
    const int quad = lane >> 3, wi = lane & 7;
    const int wm = warp * 16;
    const int b  = blockIdx.y;
    const int q0 = blockIdx.x * 64;

    const int nv = g_nvalid[b];
    const int ntiles = (nv + 127) >> 7;

    const uint32_t kfoff = (uint32_t)((((quad >> 1) * 8 + wi) * ASTR + (quad & 1) * 8) * 2);
    const uint32_t vfoff = (uint32_t)(((quad & 1) * 8 + wi) * ASTR * 2 + (quad >> 1) * 16);

    const __half* Kb = g_Kc + (size_t)b * NPAD * CH;
    const __half* Vb = g_Vc + (size_t)b * NPAD * CH;

    // prologue: prefetch K0 then V0 as separate commit groups
    {
        for (int i = tid; i < 2048; i += 128) {
            uint32_t r = i >> 4, ck = i & 15;
            cp16(sb + KOFF(0) + (r * ASTR + ck * 8) * 2, Kb + (size_t)r * CH + ck * 8);
        }
        asm volatile("cp.async.commit_group;\n");
        for (int i = tid; i < 2048; i += 128) {
            uint32_t r = i >> 4, ck = i & 15;
            cp16(sb + VOFF + (r * ASTR + ck * 8) * 2, Vb + (size_t)r * CH + ck * 8);
        }
        asm volatile("cp.async.commit_group;\n");
    }

    // resident Q fragments (pre-scaled by log2e/sqrt(C) in proj)
    uint32_t qa[8][4];
    {
        const __half* qp = g_Q + (size_t)(b * NTOK + q0 + wm + g) * CH;
#pragma unroll
        for (int ks = 0; ks < 8; ks++) {
            qa[ks][0] = *(const uint32_t*)(qp + ks * 16 + 2 * tg);
            qa[ks][1] = *(const uint32_t*)(qp + 8 * CH + ks * 16 + 2 * tg);
            qa[ks][2] = *(const uint32_t*)(qp + ks * 16 + 2 * tg + 8);
            qa[ks][3] = *(const uint32_t*)(qp + 8 * CH + ks * 16 + 2 * tg + 8);
        }
    }

    float o[16][4];
#pragma unroll
    for (int nt = 0; nt < 16; nt++) { o[nt][0] = o[nt][1] = o[nt][2] = o[nt][3] = 0.f; }
    float mrun0 = -1e30f, mrun1 = -1e30f, lsum0 = 0.f, lsum1 = 0.f;

    for (int j = 0; j < ntiles; j++) {
        if (j < ntiles - 1) {
            const int jn = j + 1;
            const uint32_t kb = sb + KOFF(jn & 1);
            const __half* kg = Kb + (size_t)(jn * 128) * CH;
            for (int i = tid; i < 2048; i += 128) {
                uint32_t r = i >> 4, ck = i & 15;
                cp16(kb + (r * ASTR + ck * 8) * 2, kg + (size_t)r * CH + ck * 8);
            }
            asm volatile("cp.async.commit_group;\n");
            asm volatile("cp.async.wait_group 1;\n" ::: "memory");
        } else {
            asm volatile("cp.async.wait_group 0;\n" ::: "memory");
        }
        __syncthreads();

        const uint32_t kfb = sb + KOFF(j & 1) + kfoff;
        const uint32_t vfb = sb + VOFF + vfoff;
        const int kbase = j * 128;

        // S = Q @ K^T with index-validity mask (nonzero only in last tile)
        float sfr[16][4];
#pragma unroll
        for (int ntp = 0; ntp < 8; ntp++) {
            float c0[4] = {0.f, 0.f, 0.f, 0.f};
            float c1[4] = {0.f, 0.f, 0.f, 0.f};
#pragma unroll
            for (int ks = 0; ks < 8; ks++) {
                uint32_t f0, f1, f2, f3;
                ldsm_x4(f0, f1, f2, f3, kfb + (uint32_t)(ntp * (16 * ASTR * 2) + ks * 32));
                mma16816(c0, qa[ks][0], qa[ks][1], qa[ks][2], qa[ks][3], f0, f1);
                mma16816(c1, qa[ks][0], qa[ks][1], qa[ks][2], qa[ks][3], f2, f3);
            }
            const int k0 = kbase + 2 * ntp * 8 + 2 * tg;
            const int k1 = kbase + (2 * ntp + 1) * 8 + 2 * tg;
            float a00 = (k0 < nv)     ? 0.f : -1e30f;
            float a01 = (k0 + 1 < nv) ? 0.f : -1e30f;
            float a10 = (k1 < nv)     ? 0.f : -1e30f;
            float a11 = (k1 + 1 < nv) ? 0.f : -1e30f;
            sfr[2 * ntp][0] = c0[0] + a00; sfr[2 * ntp][1] = c0[1] + a01;
            sfr[2 * ntp][2] = c0[2] + a00; sfr[2 * ntp][3] = c0[3] + a01;
            sfr[2 * ntp + 1][0] = c1[0] + a10; sfr[2 * ntp + 1][1] = c1[1] + a11;
            sfr[2 * ntp + 1][2] = c1[2] + a10; sfr[2 * ntp + 1][3] = c1[3] + a11;
        }

        // online softmax
        float mx0 = -1e30f, mx1 = -1e30f;
#pragma unroll
        for (int nt = 0; nt < 16; nt++) {
            mx0 = fmaxf(mx0, fmaxf(sfr[nt][0], sfr[nt][1]));
            mx1 = fmaxf(mx1, fmaxf(sfr[nt][2], sfr[nt][3]));
        }
        mx0 = fmaxf(mx0, __shfl_xor_sync(0xffffffffu, mx0, 1));
        mx0 = fmaxf(mx0, __shfl_xor_sync(0xffffffffu, mx0, 2));
        mx1 = fmaxf(mx1, __shfl_xor_sync(0xffffffffu, mx1, 1));
        mx1 = fmaxf(mx1, __shfl_xor_sync(0xffffffffu, mx1, 2));
        float mn0 = fmaxf(mrun0, mx0), mn1 = fmaxf(mrun1, mx1);
        float al0 = ex2f(mrun0 - mn0), al1 = ex2f(mrun1 - mn1);
        mrun0 = mn0; mrun1 = mn1;

        float rs0 = 0.f, rs1 = 0.f;
        uint32_t pfr[16][2];
#pragma unroll
        for (int nt = 0; nt < 16; nt++) {
            float p0 = ex2f(sfr[nt][0] - mn0), p1 = ex2f(sfr[nt][1] - mn0);
            float p2 = ex2f(sfr[nt][2] - mn1), p3 = ex2f(sfr[nt][3] - mn1);
            rs0 += p0 + p1; rs1 += p2 + p3;
            pfr[nt][0] = pack_h2(p0, p1);
            pfr[nt][1] = pack_h2(p2, p3);
        }
        rs0 += __shfl_xor_sync(0xffffffffu, rs0, 1);
        rs0 += __shfl_xor_sync(0xffffffffu, rs0, 2);
        rs1 += __shfl_xor_sync(0xffffffffu, rs1, 1);
        rs1 += __shfl_xor_sync(0xffffffffu, rs1, 2);
        lsum0 = lsum0 * al0 + rs0;
        lsum1 = lsum1 * al1 + rs1;
#pragma unroll
        for (int nt = 0; nt < 16; nt++) {
            o[nt][0] *= al0; o[nt][1] *= al0; o[nt][2] *= al1; o[nt][3] *= al1;
        }

        // O += P @ V
#pragma unroll
        for (int ntp = 0; ntp < 8; ntp++) {
#pragma unroll
            for (int ks = 0; ks < 8; ks++) {
                uint32_t f0, f1, f2, f3;
                ldsm_x4_t(f0, f1, f2, f3, vfb + (uint32_t)(ks * (16 * ASTR * 2) + ntp * 32));
                mma16816(o[2 * ntp],     pfr[2 * ks][0], pfr[2 * ks][1],
                                          pfr[2 * ks + 1][0], pfr[2 * ks + 1][1], f0, f1);
                mma16816(o[2 * ntp + 1], pfr[2 * ks][0], pfr[2 * ks][1],
                                          pfr[2 * ks + 1][0], pfr[2 * ks + 1][1], f2, f3);
            }
        }
        __syncthreads();

        if (j < ntiles - 1) {   // refill single V buffer for next tile
            const __half* vg = Vb + (size_t)((j + 1) * 128) * CH;
            for (int i = tid; i < 2048; i += 128) {
                uint32_t r = i >> 4, ck = i & 15;
                cp16(sb + VOFF + (r * ASTR + ck * 8) * 2, vg + (size_t)r * CH + ck * 8);
            }
            asm volatile("cp.async.commit_group;\n");
        }
    }

    // ---- stage x tile [128 ch][64 tok] into smem, coalesced float4 ----
    for (int i = tid; i < 128 * 16; i += 128) {
        int c = i >> 4, t4 = i & 15;
        *(float4*)&Xs[c * 68 + t4 * 4] =
            *(const float4*)(x + ((size_t)(b * CH + c)) * NTOK + q0 + t4 * 4);
    }
    __syncthreads();

    // ---- epilogue: normalize, residual, LayerNorm, coalesced store ----
    const float inv0 = 1.f / lsum0, inv1 = 1.f / lsum1;
    const int tl0 = wm + g, tl1 = wm + g + 8;
    float yv[16][4];
    float s0 = 0.f, s1 = 0.f, sq0 = 0.f, sq1 = 0.f;
#pragma unroll
    for (int nt = 0; nt < 16; nt++) {
        int c0 = nt * 8 + 2 * tg;
        float x00 = Xs[c0 * 68 + tl0];
        float x01 = Xs[(c0 + 1) * 68 + tl0];
        float x10 = Xs[c0 * 68 + tl1];
        float x11 = Xs[(c0 + 1) * 68 + tl1];
        float y0 = o[nt][0] * inv0 + x00;
        float y1 = o[nt][1] * inv0 + x01;
        float y2 = o[nt][2] * inv1 + x10;
        float y3 = o[nt][3] * inv1 + x11;
        yv[nt][0] = y0; yv[nt][1] = y1; yv[nt][2] = y2; yv[nt][3] = y3;
        s0 += y0 + y1; s1 += y2 + y3;
        sq0 += y0 * y0 + y1 * y1; sq1 += y2 * y2 + y3 * y3;
    }
    s0 += __shfl_xor_sync(0xffffffffu, s0, 1);  s0 += __shfl_xor_sync(0xffffffffu, s0, 2);
    s1 += __shfl_xor_sync(0xffffffffu, s1, 1);  s1 += __shfl_xor_sync(0xffffffffu, s1, 2);
    sq0 += __shfl_xor_sync(0xffffffffu, sq0, 1); sq0 += __shfl_xor_sync(0xffffffffu, sq0, 2);
    sq1 += __shfl_xor_sync(0xffffffffu, sq1, 1); sq1 += __shfl_xor_sync(0xffffffffu, sq1, 2);
    const float mu0 = s0 * (1.f / 128.f), mu1 = s1 * (1.f / 128.f);
    const float rstd0 = rsqrtf(sq0 * (1.f / 128.f) - mu0 * mu0 + 1e-5f);
    const float rstd1 = rsqrtf(sq1 * (1.f / 128.f) - mu1 * mu1 + 1e-5f);

#pragma unroll
    for (int nt = 0; nt < 16; nt++) {
        int c0 = nt * 8 + 2 * tg;
        float ga0 = __ldg(&gamma[c0]), ga1 = __ldg(&gamma[c0 + 1]);
        float be0 = __ldg(&beta[c0]),  be1 = __ldg(&beta[c0 + 1]);
        Ot[c0 * 68 + tl0]       = (yv[nt][0] - mu0) * rstd0 * ga0 + be0;
        Ot[(c0 + 1) * 68 + tl0] = (yv[nt][1] - mu0) * rstd0 * ga1 + be1;
        Ot[c0 * 68 + tl1]       = (yv[nt][2] - mu1) * rstd1 * ga0 + be0;
        Ot[(c0 + 1) * 68 + tl1] = (yv[nt][3] - mu1) * rstd1 * ga1 + be1;
    }
    __syncthreads();
    for (int i = tid; i < 128 * 16; i += 128) {
        int c = i >> 4, tq = i & 15;
        *(float4*)&out[((size_t)(b * CH + c)) * NTOK + q0 + tq * 4] =
            *(float4*)&Ot[c * 68 + tq * 4];
    }
}

// ============================================================================
extern "C" void kernel_launch(void* const* d_in, const int* in_sizes, int n_in,
                              void* d_out, int out_size)
{
    (void)in_sizes; (void)n_in; (void)out_size;
    const float* pf    = (const float*)d_in[0];
    const float* x     = (const float*)d_in[1];
    const float* Wq    = (const float*)d_in[2];
    const float* bq    = (const float*)d_in[3];
    const float* Wk    = (const float*)d_in[4];
    const float* bk    = (const float*)d_in[5];
    const float* Wv    = (const float*)d_in[6];
    const float* bv    = (const float*)d_in[7];
    const float* gamma = (const float*)d_in[8];
    const float* beta  = (const float*)d_in[9];
    const int*   mask  = (const int*)d_in[10];
    float* out = (float*)d_out;

    cudaFuncSetAttribute(proj_kernel, cudaFuncAttributeMaxDynamicSharedMemorySize, 72 * 1024);
    cudaFuncSetAttribute(attn_kernel, cudaFuncAttributeMaxDynamicSharedMemorySize, SMATT);

    scan_kernel<<<4, 256>>>(mask);
    dim3 g1(128, 3);
    proj_kernel<<<g1, 256, 71168>>>(pf, x, Wq, bq, Wk, bk, Wv, bv, mask);
    dim3 g2(64, 4);
    attn_kernel<<<g2, 128, SMATT>>>(x, gamma, beta, out);
}

// round 14
// speedup vs baseline: 1.0197x; 1.0197x over previous
#include <cuda_runtime.h>
#include <cuda_fp16.h>
#include <cstdint>

#define BATCH 4
#define CH    128
#define NTOK  4096
#define NPAD  4224   // NTOK + one pad tile
#define ASTR  136    // smem tile stride in halves

// ---- scratch (device globals; no runtime allocation) ----
__device__ __half g_Q [(size_t)BATCH * NTOK * CH];
__device__ __half g_Kc[(size_t)BATCH * NPAD * CH];   // compacted K (written by proj)
__device__ __half g_Vc[(size_t)BATCH * NPAD * CH];   // compacted V (written by proj)
__device__ int    g_scat[BATCH * NTOK];              // dest index for valid keys
__device__ int    g_nvalid[BATCH];

// ---- PTX helpers ----
__device__ __forceinline__ void mma16816(float* c,
    uint32_t a0, uint32_t a1, uint32_t a2, uint32_t a3,
    uint32_t b0, uint32_t b1)
{
    asm volatile(
        "mma.sync.aligned.m16n8k16.row.col.f32.f16.f16.f32 "
        "{%0,%1,%2,%3},{%4,%5,%6,%7},{%8,%9},{%0,%1,%2,%3};\n"
        : "+f"(c[0]), "+f"(c[1]), "+f"(c[2]), "+f"(c[3])
        : "r"(a0), "r"(a1), "r"(a2), "r"(a3), "r"(b0), "r"(b1));
}
__device__ __forceinline__ void ldsm_x4(uint32_t& r0, uint32_t& r1, uint32_t& r2, uint32_t& r3, uint32_t a)
{
    asm volatile("ldmatrix.sync.aligned.m8n8.x4.shared.b16 {%0,%1,%2,%3}, [%4];\n"
                 : "=r"(r0), "=r"(r1), "=r"(r2), "=r"(r3) : "r"(a));
}
__device__ __forceinline__ void ldsm_x4_t(uint32_t& r0, uint32_t& r1, uint32_t& r2, uint32_t& r3, uint32_t a)
{
    asm volatile("ldmatrix.sync.aligned.m8n8.x4.trans.shared.b16 {%0,%1,%2,%3}, [%4];\n"
                 : "=r"(r0), "=r"(r1), "=r"(r2), "=r"(r3) : "r"(a));
}
__device__ __forceinline__ float ex2f(float x)
{ float r; asm("ex2.approx.f32 %0, %1;" : "=f"(r) : "f"(x)); return r; }
__device__ __forceinline__ uint32_t pack_h2(float lo, float hi)
{ __half2 h = __floats2half2_rn(lo, hi); return *reinterpret_cast<uint32_t*>(&h); }
__device__ __forceinline__ void cp16(uint32_t d, const void* s)
{ asm volatile("cp.async.cg.shared.global [%0], [%1], 16;\n" :: "r"(d), "l"(s)); }

// ============================================================================
// Kernel S: per-batch mask scan -> scatter indices + nvalid + pad-tile zeroing
// grid = (4), 256 threads.  int4-vectorized mask reads.
// ============================================================================
__global__ __launch_bounds__(256, 1) void scan_kernel(const int* __restrict__ mask)
{
    __shared__ int ws[9];
    const int b = blockIdx.x, tid = threadIdx.x;
    const int lane = tid & 31, warp = tid >> 5;
    const int base = b * NTOK + tid * 16;

    int4 mv[4];
#pragma unroll
    for (int q = 0; q < 4; q++) mv[q] = *(const int4*)(mask + base + q * 4);
    int m[16]; int c = 0;
#pragma unroll
    for (int q = 0; q < 4; q++) {
        m[q * 4 + 0] = (mv[q].x > 0);
        m[q * 4 + 1] = (mv[q].y > 0);
        m[q * 4 + 2] = (mv[q].z > 0);
        m[q * 4 + 3] = (mv[q].w > 0);
    }
#pragma unroll
    for (int k = 0; k < 16; k++) c += m[k];
    int pre = c;
#pragma unroll
    for (int d = 1; d < 32; d <<= 1) {
        int n = __shfl_up_sync(0xffffffffu, pre, d);
        if (lane >= d) pre += n;
    }
    if (lane == 31) ws[warp] = pre;
    __syncthreads();
    if (tid == 0) {
        int s = 0;
#pragma unroll
        for (int w = 0; w < 8; w++) { int t = ws[w]; ws[w] = s; s += t; }
        ws[8] = s;
        g_nvalid[b] = s;
    }
    __syncthreads();
    int off = ws[warp] + pre - c;
#pragma unroll
    for (int k = 0; k < 16; k++) { if (m[k]) g_scat[base + k] = off++; }

    // zero-fill pad rows [nv, roundup128(nv)) — proj never writes these
    const int nv = ws[8];
    const int padEnd = ((nv + 127) >> 7) << 7;
    const uint4 z = make_uint4(0, 0, 0, 0);
    for (int i = nv * 16 + tid; i < padEnd * 16; i += 256) {
        *(uint4*)(g_Kc + (size_t)b * NPAD * CH + (size_t)i * 8) = z;
        *(uint4*)(g_Vc + (size_t)b * NPAD * CH + (size_t)i * 8) = z;
    }
}

// ============================================================================
// Kernel 1: QKV projections.  K/V rows scatter directly to compacted buffers.
// ============================================================================
__global__ __launch_bounds__(256, 1) void proj_kernel(
    const float* __restrict__ pf, const float* __restrict__ x,
    const float* __restrict__ Wq, const float* __restrict__ bq,
    const float* __restrict__ Wk, const float* __restrict__ bk,
    const float* __restrict__ Wv, const float* __restrict__ bv,
    const int* __restrict__ mask)
{
    extern __shared__ char sm[];
    __half* As  = (__half*)sm;
    __half* Ws  = (__half*)(sm + 128 * ASTR * 2);
    float*  bia = (float*)(sm + 2 * 128 * ASTR * 2);

    const int tid = threadIdx.x;
    const int p   = blockIdx.y;
    const float* src = (p == 0) ? pf : x;
    const float* W   = (p == 0) ? Wq : (p == 1 ? Wk : Wv);
    const float* bv_ = (p == 0) ? bq : (p == 1 ? bk : bv);
    const float oscale = (p == 0) ? (1.4426950408889634f / 11.313708498984761f) : 1.0f;

    const int t  = blockIdx.x;
    const int b  = t >> 5;
    const int n0 = (t & 31) * 128;

    for (int i = tid; i < 128 * 128; i += 256) {
        int c = i >> 7, tk = i & 127;
        As[tk * ASTR + c] = __float2half(src[((size_t)(b * CH + c)) * NTOK + n0 + tk]);
    }
    for (int i = tid; i < 128 * 128; i += 256) {
        int o = i >> 7, k = i & 127;
        Ws[o * ASTR + k] = __float2half(W[o * CH + k]);
    }
    if (tid < 128) bia[tid] = bv_[tid];
    __syncthreads();

    const int lane = tid & 31, warp = tid >> 5;
    const int g = lane >> 2, tg = lane & 3;
    const int wm = warp * 16;

    uint32_t qa[8][4];
#pragma unroll
    for (int ks = 0; ks < 8; ks++) {
        const __half* base = &As[(wm + g) * ASTR + ks * 16 + 2 * tg];
        qa[ks][0] = *(const uint32_t*)(base);
        qa[ks][1] = *(const uint32_t*)(base + 8 * ASTR);
        qa[ks][2] = *(const uint32_t*)(base + 8);
        qa[ks][3] = *(const uint32_t*)(base + 8 * ASTR + 8);
    }

    // destination rows for this thread's two output rows
    const int gi0 = b * NTOK + n0 + wm + g;
    const int gi1 = gi0 + 8;
    size_t row0, row1;
    bool st0 = true, st1 = true;
    __half* dst;
    if (p == 0) {
        dst = g_Q;
        row0 = (size_t)gi0 * CH;
        row1 = (size_t)gi1 * CH;
    } else {
        dst = (p == 1) ? g_Kc : g_Vc;
        st0 = (mask[gi0] > 0);
        st1 = (mask[gi1] > 0);
        row0 = st0 ? ((size_t)b * NPAD + g_scat[gi0]) * CH : 0;
        row1 = st1 ? ((size_t)b * NPAD + g_scat[gi1]) * CH : 0;
    }

#pragma unroll
    for (int nt = 0; nt < 16; nt++) {
        float acc[4] = {0.f, 0.f, 0.f, 0.f};
#pragma unroll
        for (int ks = 0; ks < 8; ks++) {
            const __half* kb = &Ws[(nt * 8 + g) * ASTR + ks * 16 + 2 * tg];
            uint32_t b0 = *(const uint32_t*)kb;
            uint32_t b1 = *(const uint32_t*)(kb + 8);
            mma16816(acc, qa[ks][0], qa[ks][1], qa[ks][2], qa[ks][3], b0, b1);
        }
        int col = nt * 8 + 2 * tg;
        float bb0 = bia[col], bb1 = bia[col + 1];
        if (st0)
            *(__half2*)&dst[row0 + col] =
                __floats2half2_rn((acc[0] + bb0) * oscale, (acc[1] + bb1) * oscale);
        if (st1)
            *(__half2*)&dst[row1 + col] =
                __floats2half2_rn((acc[2] + bb0) * oscale, (acc[3] + bb1) * oscale);
    }
}

// ============================================================================
// Kernel 2: flash attention over compacted keys + residual + LayerNorm.
// grid=(64 qtiles, 4 batch), 128 threads (4 warps x 16 queries), 2 CTAs/SM.
// smem: K0 0 | K1 34816 | V 69632   (104448 B)
// x tile prefetched (cp.async) into the DEAD K buffer during the last tile's
// compute; epilogue reads it from smem (stride-68, conflict-free).
// ============================================================================
#define KOFF(i) ((i) * 34816)
#define VOFF    69632
#define SMATT   104448

__global__ __launch_bounds__(128, 2) void attn_kernel(
    const float* __restrict__ x,
    const float* __restrict__ gamma, const float* __restrict__ beta,
    float* __restrict__ out)
{
    extern __shared__ char sm[];
    const uint32_t sb = (uint32_t)__cvta_generic_to_shared(sm);

    const int tid  = threadIdx.x;
    const int lane = tid & 31, warp = tid >> 5;
    const int g = lane >> 2, tg = lane & 3;
    const int quad = lane >> 3, wi = lane & 7;
    const int wm = warp * 16;
    const int b  = blockIdx.y;
    const int q0 = blockIdx.x * 64;

    const int nv = g_nvalid[b];
    const int ntiles = (nv + 127) >> 7;
    const uint32_t xbuf = (uint32_t)KOFF(ntiles & 1);        // dead during last tile
    float* Xs = (float*)(sm + xbuf);
    float* Ot = (float*)(sm + KOFF((ntiles + 1) & 1));       // other dead K buffer

    const uint32_t kfoff = (uint32_t)((((quad >> 1) * 8 + wi) * ASTR + (quad & 1) * 8) * 2);
    const uint32_t vfoff = (uint32_t)(((quad & 1) * 8 + wi) * ASTR * 2 + (quad >> 1) * 16);

    const __half* Kb = g_Kc + (size_t)b * NPAD * CH;
    const __half* Vb = g_Vc + (size_t)b * NPAD * CH;
    const float*  xb = x + (size_t)(b * CH) * NTOK + q0;

    // prologue: prefetch K0 then V0 as separate commit groups
    {
        for (int i = tid; i < 2048; i += 128) {
            uint32_t r = i >> 4, ck = i & 15;
            cp16(sb + KOFF(0) + (r * ASTR + ck * 8) * 2, Kb + (size_t)r * CH + ck * 8);
        }
        asm volatile("cp.async.commit_group;\n");
        for (int i = tid; i < 2048; i += 128) {
            uint32_t r = i >> 4, ck = i & 15;
            cp16(sb + VOFF + (r * ASTR + ck * 8) * 2, Vb + (size_t)r * CH + ck * 8);
        }
        if (ntiles == 1) {   // edge: hide x prefetch in prologue
            for (int i = tid; i < 2048; i += 128) {
                int c = i >> 4, t4 = i & 15;
                cp16(sb + xbuf + (uint32_t)((c * 68 + t4 * 4) * 4), xb + (size_t)c * NTOK + t4 * 4);
            }
        }
        asm volatile("cp.async.commit_group;\n");
    }

    // resident Q fragments (pre-scaled by log2e/sqrt(C) in proj)
    uint32_t qa[8][4];
    {
        const __half* qp = g_Q + (size_t)(b * NTOK + q0 + wm + g) * CH;
#pragma unroll
        for (int ks = 0; ks < 8; ks++) {
            qa[ks][0] = *(const uint32_t*)(qp + ks * 16 + 2 * tg);
            qa[ks][1] = *(const uint32_t*)(qp + 8 * CH + ks * 16 + 2 * tg);
            qa[ks][2] = *(const uint32_t*)(qp + ks * 16 + 2 * tg + 8);
            qa[ks][3] = *(const uint32_t*)(qp + 8 * CH + ks * 16 + 2 * tg + 8);
        }
    }

    float o[16][4];
#pragma unroll
    for (int nt = 0; nt < 16; nt++) { o[nt][0] = o[nt][1] = o[nt][2] = o[nt][3] = 0.f; }
    float mrun0 = -1e30f, mrun1 = -1e30f, lsum0 = 0.f, lsum1 = 0.f;

    for (int j = 0; j < ntiles; j++) {
        if (j < ntiles - 1) {
            const int jn = j + 1;
            const uint32_t kb = sb + KOFF(jn & 1);
            const __half* kg = Kb + (size_t)(jn * 128) * CH;
            for (int i = tid; i < 2048; i += 128) {
                uint32_t r = i >> 4, ck = i & 15;
                cp16(kb + (r * ASTR + ck * 8) * 2, kg + (size_t)r * CH + ck * 8);
            }
            asm volatile("cp.async.commit_group;\n");
            asm volatile("cp.async.wait_group 1;\n" ::: "memory");
        } else {
            asm volatile("cp.async.wait_group 0;\n" ::: "memory");
        }
        __syncthreads();

        const uint32_t kfb = sb + KOFF(j & 1) + kfoff;
        const uint32_t vfb = sb + VOFF + vfoff;
        const int kbase = j * 128;

        // S = Q @ K^T with index-validity mask (nonzero only in last tile)
        float sfr[16][4];
#pragma unroll
        for (int ntp = 0; ntp < 8; ntp++) {
            float c0[4] = {0.f, 0.f, 0.f, 0.f};
            float c1[4] = {0.f, 0.f, 0.f, 0.f};
#pragma unroll
            for (int ks = 0; ks < 8; ks++) {
                uint32_t f0, f1, f2, f3;
                ldsm_x4(f0, f1, f2, f3, kfb + (uint32_t)(ntp * (16 * ASTR * 2) + ks * 32));
                mma16816(c0, qa[ks][0], qa[ks][1], qa[ks][2], qa[ks][3], f0, f1);
                mma16816(c1, qa[ks][0], qa[ks][1], qa[ks][2], qa[ks][3], f2, f3);
            }
            const int k0 = kbase + 2 * ntp * 8 + 2 * tg;
            const int k1 = kbase + (2 * ntp + 1) * 8 + 2 * tg;
            float a00 = (k0 < nv)     ? 0.f : -1e30f;
            float a01 = (k0 + 1 < nv) ? 0.f : -1e30f;
            float a10 = (k1 < nv)     ? 0.f : -1e30f;
            float a11 = (k1 + 1 < nv) ? 0.f : -1e30f;
            sfr[2 * ntp][0] = c0[0] + a00; sfr[2 * ntp][1] = c0[1] + a01;
            sfr[2 * ntp][2] = c0[2] + a00; sfr[2 * ntp][3] = c0[3] + a01;
            sfr[2 * ntp + 1][0] = c1[0] + a10; sfr[2 * ntp + 1][1] = c1[1] + a11;
            sfr[2 * ntp + 1][2] = c1[2] + a10; sfr[2 * ntp + 1][3] = c1[3] + a11;
        }

        // online softmax
        float mx0 = -1e30f, mx1 = -1e30f;
#pragma unroll
        for (int nt = 0; nt < 16; nt++) {
            mx0 = fmaxf(mx0, fmaxf(sfr[nt][0], sfr[nt][1]));
            mx1 = fmaxf(mx1, fmaxf(sfr[nt][2], sfr[nt][3]));
        }
        mx0 = fmaxf(mx0, __shfl_xor_sync(0xffffffffu, mx0, 1));
        mx0 = fmaxf(mx0, __shfl_xor_sync(0xffffffffu, mx0, 2));
        mx1 = fmaxf(mx1, __shfl_xor_sync(0xffffffffu, mx1, 1));
        mx1 = fmaxf(mx1, __shfl_xor_sync(0xffffffffu, mx1, 2));
        float mn0 = fmaxf(mrun0, mx0), mn1 = fmaxf(mrun1, mx1);
        float al0 = ex2f(mrun0 - mn0), al1 = ex2f(mrun1 - mn1);
        mrun0 = mn0; mrun1 = mn1;

        float rs0 = 0.f, rs1 = 0.f;
        uint32_t pfr[16][2];
#pragma unroll
        for (int nt = 0; nt < 16; nt++) {
            float p0 = ex2f(sfr[nt][0] - mn0), p1 = ex2f(sfr[nt][1] - mn0);
            float p2 = ex2f(sfr[nt][2] - mn1), p3 = ex2f(sfr[nt][3] - mn1);
            rs0 += p0 + p1; rs1 += p2 + p3;
            pfr[nt][0] = pack_h2(p0, p1);
            pfr[nt][1] = pack_h2(p2, p3);
        }
        rs0 += __shfl_xor_sync(0xffffffffu, rs0, 1);
        rs0 += __shfl_xor_sync(0xffffffffu, rs0, 2);
        rs1 += __shfl_xor_sync(0xffffffffu, rs1, 1);
        rs1 += __shfl_xor_sync(0xffffffffu, rs1, 2);
        lsum0 = lsum0 * al0 + rs0;
        lsum1 = lsum1 * al1 + rs1;
#pragma unroll
        for (int nt = 0; nt < 16; nt++) {
            o[nt][0] *= al0; o[nt][1] *= al0; o[nt][2] *= al1; o[nt][3] *= al1;
        }

        // O += P @ V
#pragma unroll
        for (int ntp = 0; ntp < 8; ntp++) {
#pragma unroll
            for (int ks = 0; ks < 8; ks++) {
                uint32_t f0, f1, f2, f3;
                ldsm_x4_t(f0, f1, f2, f3, vfb + (uint32_t)(ks * (16 * ASTR * 2) + ntp * 32));
                mma16816(o[2 * ntp],     pfr[2 * ks][0], pfr[2 * ks][1],
                                          pfr[2 * ks + 1][0], pfr[2 * ks + 1][1], f0, f1);
                mma16816(o[2 * ntp + 1], pfr[2 * ks][0], pfr[2 * ks][1],
                                          pfr[2 * ks + 1][0], pfr[2 * ks + 1][1], f2, f3);
            }
        }
        __syncthreads();

        if (j < ntiles - 1) {   // refill single V buffer (+ hidden x prefetch)
            const __half* vg = Vb + (size_t)((j + 1) * 128) * CH;
            for (int i = tid; i < 2048; i += 128) {
                uint32_t r = i >> 4, ck = i & 15;
                cp16(sb + VOFF + (r * ASTR + ck * 8) * 2, vg + (size_t)r * CH + ck * 8);
            }
            if (j == ntiles - 2) {  // K[ntiles&1] is dead from here on: stage x
                for (int i = tid; i < 2048; i += 128) {
                    int c = i >> 4, t4 = i & 15;
                    cp16(sb + xbuf + (uint32_t)((c * 68 + t4 * 4) * 4), xb + (size_t)c * NTOK + t4 * 4);
                }
            }
            asm volatile("cp.async.commit_group;\n");
        }
    }

    // ---- epilogue: normalize, residual (x from smem), LayerNorm, store ----
    const float inv0 = 1.f / lsum0, inv1 = 1.f / lsum1;
    const int tl0 = wm + g, tl1 = wm + g + 8;
    float yv[16][4];
    float s0 = 0.f, s1 = 0.f, sq0 = 0.f, sq1 = 0.f;
#pragma unroll
    for (int nt = 0; nt < 16; nt++) {
        int c0 = nt * 8 + 2 * tg;
        float x00 = Xs[c0 * 68 + tl0];
        float x01 = Xs[(c0 + 1) * 68 + tl0];
        float x10 = Xs[c0 * 68 + tl1];
        float x11 = Xs[(c0 + 1) * 68 + tl1];
        float y0 = o[nt][0] * inv0 + x00;
        float y1 = o[nt][1] * inv0 + x01;
        float y2 = o[nt][2] * inv1 + x10;
        float y3 = o[nt][3] * inv1 + x11;
        yv[nt][0] = y0; yv[nt][1] = y1; yv[nt][2] = y2; yv[nt][3] = y3;
        s0 += y0 + y1; s1 += y2 + y3;
        sq0 += y0 * y0 + y1 * y1; sq1 += y2 * y2 + y3 * y3;
    }
    s0 += __shfl_xor_sync(0xffffffffu, s0, 1);  s0 += __shfl_xor_sync(0xffffffffu, s0, 2);
    s1 += __shfl_xor_sync(0xffffffffu, s1, 1);  s1 += __shfl_xor_sync(0xffffffffu, s1, 2);
    sq0 += __shfl_xor_sync(0xffffffffu, sq0, 1); sq0 += __shfl_xor_sync(0xffffffffu, sq0, 2);
    sq1 += __shfl_xor_sync(0xffffffffu, sq1, 1); sq1 += __shfl_xor_sync(0xffffffffu, sq1, 2);
    const float mu0 = s0 * (1.f / 128.f), mu1 = s1 * (1.f / 128.f);
    const float rstd0 = rsqrtf(sq0 * (1.f / 128.f) - mu0 * mu0 + 1e-5f);
    const float rstd1 = rsqrtf(sq1 * (1.f / 128.f) - mu1 * mu1 + 1e-5f);

#pragma unroll
    for (int nt = 0; nt < 16; nt++) {
        int c0 = nt * 8 + 2 * tg;
        float ga0 = __ldg(&gamma[c0]), ga1 = __ldg(&gamma[c0 + 1]);
        float be0 = __ldg(&beta[c0]),  be1 = __ldg(&beta[c0 + 1]);
        Ot[c0 * 68 + tl0]       = (yv[nt][0] - mu0) * rstd0 * ga0 + be0;
        Ot[(c0 + 1) * 68 + tl0] = (yv[nt][1] - mu0) * rstd0 * ga1 + be1;
        Ot[c0 * 68 + tl1]       = (yv[nt][2] - mu1) * rstd1 * ga0 + be0;
        Ot[(c0 + 1) * 68 + tl1] = (yv[nt][3] - mu1) * rstd1 * ga1 + be1;
    }
    __syncthreads();
    for (int i = tid; i < 128 * 16; i += 128) {
        int c = i >> 4, tq = i & 15;
        *(float4*)&out[((size_t)(b * CH + c)) * NTOK + q0 + tq * 4] =
            *(float4*)&Ot[c * 68 + tq * 4];
    }
}

// ============================================================================
extern "C" void kernel_launch(void* const* d_in, const int* in_sizes, int n_in,
                              void* d_out, int out_size)
{
    (void)in_sizes; (void)n_in; (void)out_size;
    const float* pf    = (const float*)d_in[0];
    const float* x     = (const float*)d_in[1];
    const float* Wq    = (const float*)d_in[2];
    const float* bq    = (const float*)d_in[3];
    const float* Wk    = (const float*)d_in[4];
    const float* bk    = (const float*)d_in[5];
    const float* Wv    = (const float*)d_in[6];
    const float* bv    = (const float*)d_in[7];
    const float* gamma = (const float*)d_in[8];
    const float* beta  = (const float*)d_in[9];
    const int*   mask  = (const int*)d_in[10];
    float* out = (float*)d_out;

    cudaFuncSetAttribute(proj_kernel, cudaFuncAttributeMaxDynamicSharedMemorySize, 72 * 1024);
    cudaFuncSetAttribute(attn_kernel, cudaFuncAttributeMaxDynamicSharedMemorySize, SMATT);

    scan_kernel<<<4, 256>>>(mask);
    dim3 g1(128, 3);
    proj_kernel<<<g1, 256, 71168>>>(pf, x, Wq, bq, Wk, bk, Wv, bv, mask);
    dim3 g2(64, 4);
    attn_kernel<<<g2, 128, SMATT>>>(x, gamma, beta, out);
}

// round 15
// speedup vs baseline: 1.0362x; 1.0162x over previous
#include <cuda_runtime.h>
#include <cuda_fp16.h>
#include <cstdint>

#define BATCH 4
#define CH    128
#define NTOK  4096
#define NPAD  4224   // NTOK + one pad tile
#define ASTR  136    // smem tile stride in halves

// ---- scratch (device globals; no runtime allocation) ----
__device__ __half g_Q [(size_t)BATCH * NTOK * CH];
__device__ __half g_Kc[(size_t)BATCH * NPAD * CH];   // compacted K (written by proj)
__device__ __half g_Vc[(size_t)BATCH * NPAD * CH];   // compacted V (written by proj)
__device__ int    g_scat[BATCH * NTOK];              // dest index for valid keys
__device__ int    g_nvalid[BATCH];

// ---- PTX helpers ----
__device__ __forceinline__ void mma16816(float* c,
    uint32_t a0, uint32_t a1, uint32_t a2, uint32_t a3,
    uint32_t b0, uint32_t b1)
{
    asm volatile(
        "mma.sync.aligned.m16n8k16.row.col.f32.f16.f16.f32 "
        "{%0,%1,%2,%3},{%4,%5,%6,%7},{%8,%9},{%0,%1,%2,%3};\n"
        : "+f"(c[0]), "+f"(c[1]), "+f"(c[2]), "+f"(c[3])
        : "r"(a0), "r"(a1), "r"(a2), "r"(a3), "r"(b0), "r"(b1));
}
__device__ __forceinline__ void ldsm_x4(uint32_t& r0, uint32_t& r1, uint32_t& r2, uint32_t& r3, uint32_t a)
{
    asm volatile("ldmatrix.sync.aligned.m8n8.x4.shared.b16 {%0,%1,%2,%3}, [%4];\n"
                 : "=r"(r0), "=r"(r1), "=r"(r2), "=r"(r3) : "r"(a));
}
__device__ __forceinline__ void ldsm_x4_t(uint32_t& r0, uint32_t& r1, uint32_t& r2, uint32_t& r3, uint32_t a)
{
    asm volatile("ldmatrix.sync.aligned.m8n8.x4.trans.shared.b16 {%0,%1,%2,%3}, [%4];\n"
                 : "=r"(r0), "=r"(r1), "=r"(r2), "=r"(r3) : "r"(a));
}
__device__ __forceinline__ float ex2f(float x)
{ float r; asm("ex2.approx.f32 %0, %1;" : "=f"(r) : "f"(x)); return r; }
__device__ __forceinline__ uint32_t pack_h2(float lo, float hi)
{ __half2 h = __floats2half2_rn(lo, hi); return *reinterpret_cast<uint32_t*>(&h); }
__device__ __forceinline__ void cp16(uint32_t d, const void* s)
{ asm volatile("cp.async.cg.shared.global [%0], [%1], 16;\n" :: "r"(d), "l"(s)); }

// ============================================================================
// Kernel S: per-batch mask scan -> scatter indices + nvalid + pad-tile zeroing
// grid = (4), 256 threads.  int4-vectorized mask reads.
// ============================================================================
__global__ __launch_bounds__(256, 1) void scan_kernel(const int* __restrict__ mask)
{
    __shared__ int ws[9];
    const int b = blockIdx.x, tid = threadIdx.x;
    const int lane = tid & 31, warp = tid >> 5;
    const int base = b * NTOK + tid * 16;

    int4 mv[4];
#pragma unroll
    for (int q = 0; q < 4; q++) mv[q] = *(const int4*)(mask + base + q * 4);
    int m[16]; int c = 0;
#pragma unroll
    for (int q = 0; q < 4; q++) {
        m[q * 4 + 0] = (mv[q].x > 0);
        m[q * 4 + 1] = (mv[q].y > 0);
        m[q * 4 + 2] = (mv[q].z > 0);
        m[q * 4 + 3] = (mv[q].w > 0);
    }
#pragma unroll
    for (int k = 0; k < 16; k++) c += m[k];
    int pre = c;
#pragma unroll
    for (int d = 1; d < 32; d <<= 1) {
        int n = __shfl_up_sync(0xffffffffu, pre, d);
        if (lane >= d) pre += n;
    }
    if (lane == 31) ws[warp] = pre;
    __syncthreads();
    if (tid == 0) {
        int s = 0;
#pragma unroll
        for (int w = 0; w < 8; w++) { int t = ws[w]; ws[w] = s; s += t; }
        ws[8] = s;
        g_nvalid[b] = s;
    }
    __syncthreads();
    int off = ws[warp] + pre - c;
#pragma unroll
    for (int k = 0; k < 16; k++) { if (m[k]) g_scat[base + k] = off++; }

    // zero-fill pad rows [nv, roundup128(nv)) — proj never writes these
    const int nv = ws[8];
    const int padEnd = ((nv + 127) >> 7) << 7;
    const uint4 z = make_uint4(0, 0, 0, 0);
    for (int i = nv * 16 + tid; i < padEnd * 16; i += 256) {
        *(uint4*)(g_Kc + (size_t)b * NPAD * CH + (size_t)i * 8) = z;
        *(uint4*)(g_Vc + (size_t)b * NPAD * CH + (size_t)i * 8) = z;
    }
}

// ============================================================================
// Kernel 1: QKV projections.  K/V rows scatter directly to compacted buffers.
// ============================================================================
__global__ __launch_bounds__(256, 1) void proj_kernel(
    const float* __restrict__ pf, const float* __restrict__ x,
    const float* __restrict__ Wq, const float* __restrict__ bq,
    const float* __restrict__ Wk, const float* __restrict__ bk,
    const float* __restrict__ Wv, const float* __restrict__ bv,
    const int* __restrict__ mask)
{
    extern __shared__ char sm[];
    __half* As  = (__half*)sm;
    __half* Ws  = (__half*)(sm + 128 * ASTR * 2);
    float*  bia = (float*)(sm + 2 * 128 * ASTR * 2);

    const int tid = threadIdx.x;
    const int p   = blockIdx.y;
    const float* src = (p == 0) ? pf : x;
    const float* W   = (p == 0) ? Wq : (p == 1 ? Wk : Wv);
    const float* bv_ = (p == 0) ? bq : (p == 1 ? bk : bv);
    const float oscale = (p == 0) ? (1.4426950408889634f / 11.313708498984761f) : 1.0f;

    const int t  = blockIdx.x;
    const int b  = t >> 5;
    const int n0 = (t & 31) * 128;

    for (int i = tid; i < 128 * 128; i += 256) {
        int c = i >> 7, tk = i & 127;
        As[tk * ASTR + c] = __float2half(src[((size_t)(b * CH + c)) * NTOK + n0 + tk]);
    }
    for (int i = tid; i < 128 * 128; i += 256) {
        int o = i >> 7, k = i & 127;
        Ws[o * ASTR + k] = __float2half(W[o * CH + k]);
    }
    if (tid < 128) bia[tid] = bv_[tid];
    __syncthreads();

    const int lane = tid & 31, warp = tid >> 5;
    const int g = lane >> 2, tg = lane & 3;
    const int wm = warp * 16;

    uint32_t qa[8][4];
#pragma unroll
    for (int ks = 0; ks < 8; ks++) {
        const __half* base = &As[(wm + g) * ASTR + ks * 16 + 2 * tg];
        qa[ks][0] = *(const uint32_t*)(base);
        qa[ks][1] = *(const uint32_t*)(base + 8 * ASTR);
        qa[ks][2] = *(const uint32_t*)(base + 8);
        qa[ks][3] = *(const uint32_t*)(base + 8 * ASTR + 8);
    }

    // destination rows for this thread's two output rows
    const int gi0 = b * NTOK + n0 + wm + g;
    const int gi1 = gi0 + 8;
    size_t row0, row1;
    bool st0 = true, st1 = true;
    __half* dst;
    if (p == 0) {
        dst = g_Q;
        row0 = (size_t)gi0 * CH;
        row1 = (size_t)gi1 * CH;
    } else {
        dst = (p == 1) ? g_Kc : g_Vc;
        st0 = (mask[gi0] > 0);
        st1 = (mask[gi1] > 0);
        row0 = st0 ? ((size_t)b * NPAD + g_scat[gi0]) * CH : 0;
        row1 = st1 ? ((size_t)b * NPAD + g_scat[gi1]) * CH : 0;
    }

#pragma unroll
    for (int nt = 0; nt < 16; nt++) {
        float acc[4] = {0.f, 0.f, 0.f, 0.f};
#pragma unroll
        for (int ks = 0; ks < 8; ks++) {
            const __half* kb = &Ws[(nt * 8 + g) * ASTR + ks * 16 + 2 * tg];
            uint32_t b0 = *(const uint32_t*)kb;
            uint32_t b1 = *(const uint32_t*)(kb + 8);
            mma16816(acc, qa[ks][0], qa[ks][1], qa[ks][2], qa[ks][3], b0, b1);
        }
        int col = nt * 8 + 2 * tg;
        float bb0 = bia[col], bb1 = bia[col + 1];
        if (st0)
            *(__half2*)&dst[row0 + col] =
                __floats2half2_rn((acc[0] + bb0) * oscale, (acc[1] + bb1) * oscale);
        if (st1)
            *(__half2*)&dst[row1 + col] =
                __floats2half2_rn((acc[2] + bb0) * oscale, (acc[3] + bb1) * oscale);
    }
}

// ============================================================================
// Kernel 2: flash attention over compacted keys + residual + LayerNorm.
// grid=(64 qtiles, 4 batch), 128 threads (4 warps x 16 queries), 2 CTAs/SM.
// S and PV mma loops are ks-OUTER / ntp-INNER: 16 independent accumulators
// per inner sweep -> deep ILP instead of 8-long serial accumulator chains.
// smem: K0 0 | K1 34816 | V 69632   (104448 B)
// ============================================================================
#define KOFF(i) ((i) * 34816)
#define VOFF    69632
#define SMATT   104448

__global__ __launch_bounds__(128, 2) void attn_kernel(
    const float* __restrict__ x,
    const float* __restrict__ gamma, const float* __restrict__ beta,
    float* __restrict__ out)
{
    extern __shared__ char sm[];
    const uint32_t sb = (uint32_t)__cvta_generic_to_shared(sm);
    float* Ot = (float*)sm;   // epilogue staging [128 ch][68], overlaps K0

    const int tid  = threadIdx.x;
    const int lane = tid & 31, warp = tid >> 5;
    const int g = lane >> 2, tg = lane & 3;
    const int quad = lane >> 3, wi = lane & 7;
    const int wm = warp * 16;
    const int b  = blockIdx.y;
    const int q0 = blockIdx.x * 64;

    const int nv = g_nvalid[b];
    const int ntiles = (nv + 127) >> 7;

    const uint32_t kfoff = (uint32_t)((((quad >> 1) * 8 + wi) * ASTR + (quad & 1) * 8) * 2);
    const uint32_t vfoff = (uint32_t)(((quad & 1) * 8 + wi) * ASTR * 2 + (quad >> 1) * 16);

    const __half* Kb = g_Kc + (size_t)b * NPAD * CH;
    const __half* Vb = g_Vc + (size_t)b * NPAD * CH;

    // prologue: prefetch K0 then V0 as separate commit groups
    {
        for (int i = tid; i < 2048; i += 128) {
            uint32_t r = i >> 4, ck = i & 15;
            cp16(sb + KOFF(0) + (r * ASTR + ck * 8) * 2, Kb + (size_t)r * CH + ck * 8);
        }
        asm volatile("cp.async.commit_group;\n");
        for (int i = tid; i < 2048; i += 128) {
            uint32_t r = i >> 4, ck = i & 15;
            cp16(sb + VOFF + (r * ASTR + ck * 8) * 2, Vb + (size_t)r * CH + ck * 8);
        }
        asm volatile("cp.async.commit_group;\n");
    }

    // resident Q fragments (pre-scaled by log2e/sqrt(C) in proj)
    uint32_t qa[8][4];
    {
        const __half* qp = g_Q + (size_t)(b * NTOK + q0 + wm + g) * CH;
#pragma unroll
        for (int ks = 0; ks < 8; ks++) {
            qa[ks][0] = *(const uint32_t*)(qp + ks * 16 + 2 * tg);
            qa[ks][1] = *(const uint32_t*)(qp + 8 * CH + ks * 16 + 2 * tg);
            qa[ks][2] = *(const uint32_t*)(qp + ks * 16 + 2 * tg + 8);
            qa[ks][3] = *(const uint32_t*)(qp + 8 * CH + ks * 16 + 2 * tg + 8);
        }
    }

    float o[16][4];
#pragma unroll
    for (int nt = 0; nt < 16; nt++) { o[nt][0] = o[nt][1] = o[nt][2] = o[nt][3] = 0.f; }
    float mrun0 = -1e30f, mrun1 = -1e30f, lsum0 = 0.f, lsum1 = 0.f;

    for (int j = 0; j < ntiles; j++) {
        if (j < ntiles - 1) {
            const int jn = j + 1;
            const uint32_t kb = sb + KOFF(jn & 1);
            const __half* kg = Kb + (size_t)(jn * 128) * CH;
            for (int i = tid; i < 2048; i += 128) {
                uint32_t r = i >> 4, ck = i & 15;
                cp16(kb + (r * ASTR + ck * 8) * 2, kg + (size_t)r * CH + ck * 8);
            }
            asm volatile("cp.async.commit_group;\n");
            asm volatile("cp.async.wait_group 1;\n" ::: "memory");
        } else {
            asm volatile("cp.async.wait_group 0;\n" ::: "memory");
        }
        __syncthreads();

        const uint32_t kfb = sb + KOFF(j & 1) + kfoff;
        const uint32_t vfb = sb + VOFF + vfoff;
        const int kbase = j * 128;

        // S = Q @ K^T  — ks outer, ntp inner: 16 independent accumulators
        float sfr[16][4];
#pragma unroll
        for (int nt = 0; nt < 16; nt++) { sfr[nt][0] = sfr[nt][1] = sfr[nt][2] = sfr[nt][3] = 0.f; }
#pragma unroll
        for (int ks = 0; ks < 8; ks++) {
#pragma unroll
            for (int ntp = 0; ntp < 8; ntp++) {
                uint32_t f0, f1, f2, f3;
                ldsm_x4(f0, f1, f2, f3, kfb + (uint32_t)(ntp * (16 * ASTR * 2) + ks * 32));
                mma16816(sfr[2 * ntp],     qa[ks][0], qa[ks][1], qa[ks][2], qa[ks][3], f0, f1);
                mma16816(sfr[2 * ntp + 1], qa[ks][0], qa[ks][1], qa[ks][2], qa[ks][3], f2, f3);
            }
        }
        // additive validity mask (nonzero only in last tile)
#pragma unroll
        for (int nt = 0; nt < 16; nt++) {
            const int k = kbase + nt * 8 + 2 * tg;
            float a0 = (k < nv)     ? 0.f : -1e30f;
            float a1 = (k + 1 < nv) ? 0.f : -1e30f;
            sfr[nt][0] += a0; sfr[nt][1] += a1;
            sfr[nt][2] += a0; sfr[nt][3] += a1;
        }

        // online softmax
        float mx0 = -1e30f, mx1 = -1e30f;
#pragma unroll
        for (int nt = 0; nt < 16; nt++) {
            mx0 = fmaxf(mx0, fmaxf(sfr[nt][0], sfr[nt][1]));
            mx1 = fmaxf(mx1, fmaxf(sfr[nt][2], sfr[nt][3]));
        }
        mx0 = fmaxf(mx0, __shfl_xor_sync(0xffffffffu, mx0, 1));
        mx0 = fmaxf(mx0, __shfl_xor_sync(0xffffffffu, mx0, 2));
        mx1 = fmaxf(mx1, __shfl_xor_sync(0xffffffffu, mx1, 1));
        mx1 = fmaxf(mx1, __shfl_xor_sync(0xffffffffu, mx1, 2));
        float mn0 = fmaxf(mrun0, mx0), mn1 = fmaxf(mrun1, mx1);
        float al0 = ex2f(mrun0 - mn0), al1 = ex2f(mrun1 - mn1);
        mrun0 = mn0; mrun1 = mn1;

        float rs0 = 0.f, rs1 = 0.f;
        uint32_t pfr[16][2];
#pragma unroll
        for (int nt = 0; nt < 16; nt++) {
            float p0 = ex2f(sfr[nt][0] - mn0), p1 = ex2f(sfr[nt][1] - mn0);
            float p2 = ex2f(sfr[nt][2] - mn1), p3 = ex2f(sfr[nt][3] - mn1);
            rs0 += p0 + p1; rs1 += p2 + p3;
            pfr[nt][0] = pack_h2(p0, p1);
            pfr[nt][1] = pack_h2(p2, p3);
        }
        rs0 += __shfl_xor_sync(0xffffffffu, rs0, 1);
        rs0 += __shfl_xor_sync(0xffffffffu, rs0, 2);
        rs1 += __shfl_xor_sync(0xffffffffu, rs1, 1);
        rs1 += __shfl_xor_sync(0xffffffffu, rs1, 2);
        lsum0 = lsum0 * al0 + rs0;
        lsum1 = lsum1 * al1 + rs1;
#pragma unroll
        for (int nt = 0; nt < 16; nt++) {
            o[nt][0] *= al0; o[nt][1] *= al0; o[nt][2] *= al1; o[nt][3] *= al1;
        }

        // O += P @ V  — ks outer, ntp inner: 16 independent accumulators
#pragma unroll
        for (int ks = 0; ks < 8; ks++) {
#pragma unroll
            for (int ntp = 0; ntp < 8; ntp++) {
                uint32_t f0, f1, f2, f3;
                ldsm_x4_t(f0, f1, f2, f3, vfb + (uint32_t)(ks * (16 * ASTR * 2) + ntp * 32));
                mma16816(o[2 * ntp],     pfr[2 * ks][0], pfr[2 * ks][1],
                                          pfr[2 * ks + 1][0], pfr[2 * ks + 1][1], f0, f1);
                mma16816(o[2 * ntp + 1], pfr[2 * ks][0], pfr[2 * ks][1],
                                          pfr[2 * ks + 1][0], pfr[2 * ks + 1][1], f2, f3);
            }
        }
        __syncthreads();

        if (j < ntiles - 1) {   // refill single V buffer for next tile
            const __half* vg = Vb + (size_t)((j + 1) * 128) * CH;
            for (int i = tid; i < 2048; i += 128) {
                uint32_t r = i >> 4, ck = i & 15;
                cp16(sb + VOFF + (r * ASTR + ck * 8) * 2, vg + (size_t)r * CH + ck * 8);
            }
            asm volatile("cp.async.commit_group;\n");
        }
    }

    // ---- epilogue: normalize, residual, LayerNorm, coalesced store ----
    const float inv0 = 1.f / lsum0, inv1 = 1.f / lsum1;
    const int t0 = q0 + wm + g, t1 = t0 + 8;
    float yv[16][4];
    float s0 = 0.f, s1 = 0.f, sq0 = 0.f, sq1 = 0.f;
#pragma unroll
    for (int nt = 0; nt < 16; nt++) {
        int c0 = nt * 8 + 2 * tg;
        float x00 = x[((size_t)(b * CH + c0)) * NTOK + t0];
        float x01 = x[((size_t)(b * CH + c0 + 1)) * NTOK + t0];
        float x10 = x[((size_t)(b * CH + c0)) * NTOK + t1];
        float x11 = x[((size_t)(b * CH + c0 + 1)) * NTOK + t1];
        float y0 = o[nt][0] * inv0 + x00;
        float y1 = o[nt][1] * inv0 + x01;
        float y2 = o[nt][2] * inv1 + x10;
        float y3 = o[nt][3] * inv1 + x11;
        yv[nt][0] = y0; yv[nt][1] = y1; yv[nt][2] = y2; yv[nt][3] = y3;
        s0 += y0 + y1; s1 += y2 + y3;
        sq0 += y0 * y0 + y1 * y1; sq1 += y2 * y2 + y3 * y3;
    }
    s0 += __shfl_xor_sync(0xffffffffu, s0, 1);  s0 += __shfl_xor_sync(0xffffffffu, s0, 2);
    s1 += __shfl_xor_sync(0xffffffffu, s1, 1);  s1 += __shfl_xor_sync(0xffffffffu, s1, 2);
    sq0 += __shfl_xor_sync(0xffffffffu, sq0, 1); sq0 += __shfl_xor_sync(0xffffffffu, sq0, 2);
    sq1 += __shfl_xor_sync(0xffffffffu, sq1, 1); sq1 += __shfl_xor_sync(0xffffffffu, sq1, 2);
    const float mu0 = s0 * (1.f / 128.f), mu1 = s1 * (1.f / 128.f);
    const float rstd0 = rsqrtf(sq0 * (1.f / 128.f) - mu0 * mu0 + 1e-5f);
    const float rstd1 = rsqrtf(sq1 * (1.f / 128.f) - mu1 * mu1 + 1e-5f);

    const int tl0 = wm + g, tl1 = wm + g + 8;
#pragma unroll
    for (int nt = 0; nt < 16; nt++) {
        int c0 = nt * 8 + 2 * tg;
        float ga0 = __ldg(&gamma[c0]), ga1 = __ldg(&gamma[c0 + 1]);
        float be0 = __ldg(&beta[c0]),  be1 = __ldg(&beta[c0 + 1]);
        Ot[c0 * 68 + tl0]       = (yv[nt][0] - mu0) * rstd0 * ga0 + be0;
        Ot[(c0 + 1) * 68 + tl0] = (yv[nt][1] - mu0) * rstd0 * ga1 + be1;
        Ot[c0 * 68 + tl1]       = (yv[nt][2] - mu1) * rstd1 * ga0 + be0;
        Ot[(c0 + 1) * 68 + tl1] = (yv[nt][3] - mu1) * rstd1 * ga1 + be1;
    }
    __syncthreads();
    for (int i = tid; i < 128 * 16; i += 128) {
        int c = i >> 4, tq = i & 15;
        *(float4*)&out[((size_t)(b * CH + c)) * NTOK + q0 + tq * 4] =
            *(float4*)&Ot[c * 68 + tq * 4];
    }
}

// ============================================================================
extern "C" void kernel_launch(void* const* d_in, const int* in_sizes, int n_in,
                              void* d_out, int out_size)
{
    (void)in_sizes; (void)n_in; (void)out_size;
    const float* pf    = (const float*)d_in[0];
    const float* x     = (const float*)d_in[1];
    const float* Wq    = (const float*)d_in[2];
    const float* bq    = (const float*)d_in[3];
    const float* Wk    = (const float*)d_in[4];
    const float* bk    = (const float*)d_in[5];
    const float* Wv    = (const float*)d_in[6];
    const float* bv    = (const float*)d_in[7];
    const float* gamma = (const float*)d_in[8];
    const float* beta  = (const float*)d_in[9];
    const int*   mask  = (const int*)d_in[10];
    float* out = (float*)d_out;

    cudaFuncSetAttribute(proj_kernel, cudaFuncAttributeMaxDynamicSharedMemorySize, 72 * 1024);
    cudaFuncSetAttribute(attn_kernel, cudaFuncAttributeMaxDynamicSharedMemorySize, SMATT);

    scan_kernel<<<4, 256>>>(mask);
    dim3 g1(128, 3);
    proj_kernel<<<g1, 256, 71168>>>(pf, x, Wq, bq, Wk, bk, Wv, bv, mask);
    dim3 g2(64, 4);
    attn_kernel<<<g2, 128, SMATT>>>(x, gamma, beta, out);
}

// round 16
// speedup vs baseline: 1.0769x; 1.0393x over previous
#include <cuda_runtime.h>
#include <cuda_fp16.h>
#include <cstdint>

#define BATCH 4
#define CH    128
#define NTOK  4096
#define NPAD  4224   // NTOK + one pad tile
#define ASTR  136    // smem tile stride in halves

// ---- scratch (device globals; no runtime allocation) ----
__device__ __half g_Q [(size_t)BATCH * NTOK * CH];
__device__ __half g_Kc[(size_t)BATCH * NPAD * CH];   // compacted K (written by proj)
__device__ __half g_Vc[(size_t)BATCH * NPAD * CH];   // compacted V (written by proj)
__device__ int    g_scat[BATCH * NTOK];              // dest index for valid keys
__device__ int    g_nvalid[BATCH];
__device__ unsigned g_flag[BATCH];                   // scan-done flags (per batch)

// ---- PTX helpers ----
__device__ __forceinline__ void mma16816(float* c,
    uint32_t a0, uint32_t a1, uint32_t a2, uint32_t a3,
    uint32_t b0, uint32_t b1)
{
    asm volatile(
        "mma.sync.aligned.m16n8k16.row.col.f32.f16.f16.f32 "
        "{%0,%1,%2,%3},{%4,%5,%6,%7},{%8,%9},{%0,%1,%2,%3};\n"
        : "+f"(c[0]), "+f"(c[1]), "+f"(c[2]), "+f"(c[3])
        : "r"(a0), "r"(a1), "r"(a2), "r"(a3), "r"(b0), "r"(b1));
}
__device__ __forceinline__ void ldsm_x4(uint32_t& r0, uint32_t& r1, uint32_t& r2, uint32_t& r3, uint32_t a)
{
    asm volatile("ldmatrix.sync.aligned.m8n8.x4.shared.b16 {%0,%1,%2,%3}, [%4];\n"
                 : "=r"(r0), "=r"(r1), "=r"(r2), "=r"(r3) : "r"(a));
}
__device__ __forceinline__ void ldsm_x4_t(uint32_t& r0, uint32_t& r1, uint32_t& r2, uint32_t& r3, uint32_t a)
{
    asm volatile("ldmatrix.sync.aligned.m8n8.x4.trans.shared.b16 {%0,%1,%2,%3}, [%4];\n"
                 : "=r"(r0), "=r"(r1), "=r"(r2), "=r"(r3) : "r"(a));
}
__device__ __forceinline__ float ex2f(float x)
{ float r; asm("ex2.approx.f32 %0, %1;" : "=f"(r) : "f"(x)); return r; }
__device__ __forceinline__ uint32_t pack_h2(float lo, float hi)
{ __half2 h = __floats2half2_rn(lo, hi); return *reinterpret_cast<uint32_t*>(&h); }
__device__ __forceinline__ void cp16(uint32_t d, const void* s)
{ asm volatile("cp.async.cg.shared.global [%0], [%1], 16;\n" :: "r"(d), "l"(s)); }

// ============================================================================
// Kernel 1: QKV projections with INLINE mask scan.
// grid = (128, 3).  CTAs (y==0, x&31==0) scan batch x>>5 first, set g_flag.
// K/V CTAs (y=1,2) spin on g_flag[b] after their fill phase, then scatter
// rows directly to the compacted buffers via g_scat.
// ============================================================================
__global__ __launch_bounds__(256, 1) void proj_kernel(
    const float* __restrict__ pf, const float* __restrict__ x,
    const float* __restrict__ Wq, const float* __restrict__ bq,
    const float* __restrict__ Wk, const float* __restrict__ bk,
    const float* __restrict__ Wv, const float* __restrict__ bv,
    const int* __restrict__ mask)
{
    extern __shared__ char sm[];
    __half* As  = (__half*)sm;
    __half* Ws  = (__half*)(sm + 128 * ASTR * 2);
    float*  bia = (float*)(sm + 2 * 128 * ASTR * 2);

    const int tid = threadIdx.x;
    const int p   = blockIdx.y;
    const int t   = blockIdx.x;
    const int b   = t >> 5;
    const int n0  = (t & 31) * 128;
    const int lane = tid & 31, warp = tid >> 5;

    // ---- inline scan (4 designated CTAs, one per batch) ----
    if (p == 0 && (t & 31) == 0) {
        __shared__ int ws[9];
        const int base = b * NTOK + tid * 16;
        int4 mv[4];
#pragma unroll
        for (int q = 0; q < 4; q++) mv[q] = *(const int4*)(mask + base + q * 4);
        int m[16]; int c = 0;
#pragma unroll
        for (int q = 0; q < 4; q++) {
            m[q * 4 + 0] = (mv[q].x > 0);
            m[q * 4 + 1] = (mv[q].y > 0);
            m[q * 4 + 2] = (mv[q].z > 0);
            m[q * 4 + 3] = (mv[q].w > 0);
        }
#pragma unroll
        for (int k = 0; k < 16; k++) c += m[k];
        int pre = c;
#pragma unroll
        for (int d = 1; d < 32; d <<= 1) {
            int n = __shfl_up_sync(0xffffffffu, pre, d);
            if (lane >= d) pre += n;
        }
        if (lane == 31) ws[warp] = pre;
        __syncthreads();
        if (tid == 0) {
            int s = 0;
#pragma unroll
            for (int w = 0; w < 8; w++) { int tv = ws[w]; ws[w] = s; s += tv; }
            ws[8] = s;
            g_nvalid[b] = s;
        }
        __syncthreads();
        int off = ws[warp] + pre - c;
#pragma unroll
        for (int k = 0; k < 16; k++) { if (m[k]) g_scat[base + k] = off++; }

        // zero-fill pad rows [nv, roundup128(nv)) — K/V CTAs never write these
        const int nv = ws[8];
        const int padEnd = ((nv + 127) >> 7) << 7;
        const uint4 z = make_uint4(0, 0, 0, 0);
        for (int i = nv * 16 + tid; i < padEnd * 16; i += 256) {
            *(uint4*)(g_Kc + (size_t)b * NPAD * CH + (size_t)i * 8) = z;
            *(uint4*)(g_Vc + (size_t)b * NPAD * CH + (size_t)i * 8) = z;
        }
        __syncthreads();
        __threadfence();
        if (tid == 0) atomicExch(&g_flag[b], 1u);
        __syncthreads();   // smem (ws) dead before fill reuses the region
    }

    const float* src = (p == 0) ? pf : x;
    const float* W   = (p == 0) ? Wq : (p == 1 ? Wk : Wv);
    const float* bv_ = (p == 0) ? bq : (p == 1 ? bk : bv);
    const float oscale = (p == 0) ? (1.4426950408889634f / 11.313708498984761f) : 1.0f;

    for (int i = tid; i < 128 * 128; i += 256) {
        int c = i >> 7, tk = i & 127;
        As[tk * ASTR + c] = __float2half(src[((size_t)(b * CH + c)) * NTOK + n0 + tk]);
    }
    for (int i = tid; i < 128 * 128; i += 256) {
        int o = i >> 7, k = i & 127;
        Ws[o * ASTR + k] = __float2half(W[o * CH + k]);
    }
    if (tid < 128) bia[tid] = bv_[tid];
    __syncthreads();

    const int g = lane >> 2, tg = lane & 3;
    const int wm = warp * 16;

    uint32_t qa[8][4];
#pragma unroll
    for (int ks = 0; ks < 8; ks++) {
        const __half* base = &As[(wm + g) * ASTR + ks * 16 + 2 * tg];
        qa[ks][0] = *(const uint32_t*)(base);
        qa[ks][1] = *(const uint32_t*)(base + 8 * ASTR);
        qa[ks][2] = *(const uint32_t*)(base + 8);
        qa[ks][3] = *(const uint32_t*)(base + 8 * ASTR + 8);
    }

    // K/V CTAs: wait for this batch's scan before touching g_scat
    if (p != 0) {
        if (tid == 0) {
            while (atomicAdd(&g_flag[b], 0u) == 0u) __nanosleep(100);
        }
        __syncthreads();
    }

    // destination rows for this thread's two output rows
    const int gi0 = b * NTOK + n0 + wm + g;
    const int gi1 = gi0 + 8;
    size_t row0, row1;
    bool st0 = true, st1 = true;
    __half* dst;
    if (p == 0) {
        dst = g_Q;
        row0 = (size_t)gi0 * CH;
        row1 = (size_t)gi1 * CH;
    } else {
        dst = (p == 1) ? g_Kc : g_Vc;
        st0 = (mask[gi0] > 0);
        st1 = (mask[gi1] > 0);
        row0 = st0 ? ((size_t)b * NPAD + g_scat[gi0]) * CH : 0;
        row1 = st1 ? ((size_t)b * NPAD + g_scat[gi1]) * CH : 0;
    }

#pragma unroll
    for (int nt = 0; nt < 16; nt++) {
        float acc[4] = {0.f, 0.f, 0.f, 0.f};
#pragma unroll
        for (int ks = 0; ks < 8; ks++) {
            const __half* kb = &Ws[(nt * 8 + g) * ASTR + ks * 16 + 2 * tg];
            uint32_t b0 = *(const uint32_t*)kb;
            uint32_t b1 = *(const uint32_t*)(kb + 8);
            mma16816(acc, qa[ks][0], qa[ks][1], qa[ks][2], qa[ks][3], b0, b1);
        }
        int col = nt * 8 + 2 * tg;
        float bb0 = bia[col], bb1 = bia[col + 1];
        if (st0)
            *(__half2*)&dst[row0 + col] =
                __floats2half2_rn((acc[0] + bb0) * oscale, (acc[1] + bb1) * oscale);
        if (st1)
            *(__half2*)&dst[row1 + col] =
                __floats2half2_rn((acc[2] + bb0) * oscale, (acc[3] + bb1) * oscale);
    }
}

// ============================================================================
// Kernel 2: flash attention over compacted keys + residual + LayerNorm.
// grid=(64 qtiles, 4 batch), 128 threads (4 warps x 16 queries), 2 CTAs/SM.
// smem: K0 0 | K1 34816 | V 69632   (104448 B)
// ============================================================================
#define KOFF(i) ((i) * 34816)
#define VOFF    69632
#define SMATT   104448

__global__ __launch_bounds__(128, 2) void attn_kernel(
    const float* __restrict__ x,
    const float* __restrict__ gamma, const float* __restrict__ beta,
    float* __restrict__ out)
{
    extern __shared__ char sm[];
    const uint32_t sb = (uint32_t)__cvta_generic_to_shared(sm);
    float* Ot = (float*)sm;   // epilogue staging [128 ch][68], overlaps K0

    const int tid  = threadIdx.x;
    const int lane = tid & 31, warp = tid >> 5;
    const int g = lane >> 2, tg = lane & 3;
    const int quad = lane >> 3, wi = lane & 7;
    const int wm = warp * 16;
    const int b  = blockIdx.y;
    const int q0 = blockIdx.x * 64;

    const int nv = g_nvalid[b];
    const int ntiles = (nv + 127) >> 7;

    const uint32_t kfoff = (uint32_t)((((quad >> 1) * 8 + wi) * ASTR + (quad & 1) * 8) * 2);
    const uint32_t vfoff = (uint32_t)(((quad & 1) * 8 + wi) * ASTR * 2 + (quad >> 1) * 16);

    const __half* Kb = g_Kc + (size_t)b * NPAD * CH;
    const __half* Vb = g_Vc + (size_t)b * NPAD * CH;

    // prologue: prefetch K0 then V0 as separate commit groups
    {
        for (int i = tid; i < 2048; i += 128) {
            uint32_t r = i >> 4, ck = i & 15;
            cp16(sb + KOFF(0) + (r * ASTR + ck * 8) * 2, Kb + (size_t)r * CH + ck * 8);
        }
        asm volatile("cp.async.commit_group;\n");
        for (int i = tid; i < 2048; i += 128) {
            uint32_t r = i >> 4, ck = i & 15;
            cp16(sb + VOFF + (r * ASTR + ck * 8) * 2, Vb + (size_t)r * CH + ck * 8);
        }
        asm volatile("cp.async.commit_group;\n");
    }

    // resident Q fragments (pre-scaled by log2e/sqrt(C) in proj)
    uint32_t qa[8][4];
    {
        const __half* qp = g_Q + (size_t)(b * NTOK + q0 + wm + g) * CH;
#pragma unroll
        for (int ks = 0; ks < 8; ks++) {
            qa[ks][0] = *(const uint32_t*)(qp + ks * 16 + 2 * tg);
            qa[ks][1] = *(const uint32_t*)(qp + 8 * CH + ks * 16 + 2 * tg);
            qa[ks][2] = *(const uint32_t*)(qp + ks * 16 + 2 * tg + 8);
            qa[ks][3] = *(const uint32_t*)(qp + 8 * CH + ks * 16 + 2 * tg + 8);
        }
    }

    float o[16][4];
#pragma unroll
    for (int nt = 0; nt < 16; nt++) { o[nt][0] = o[nt][1] = o[nt][2] = o[nt][3] = 0.f; }
    float mrun0 = -1e30f, mrun1 = -1e30f, lsum0 = 0.f, lsum1 = 0.f;

    for (int j = 0; j < ntiles; j++) {
        if (j < ntiles - 1) {
            const int jn = j + 1;
            const uint32_t kb = sb + KOFF(jn & 1);
            const __half* kg = Kb + (size_t)(jn * 128) * CH;
            for (int i = tid; i < 2048; i += 128) {
                uint32_t r = i >> 4, ck = i & 15;
                cp16(kb + (r * ASTR + ck * 8) * 2, kg + (size_t)r * CH + ck * 8);
            }
            asm volatile("cp.async.commit_group;\n");
            asm volatile("cp.async.wait_group 1;\n" ::: "memory");
        } else {
            asm volatile("cp.async.wait_group 0;\n" ::: "memory");
        }
        __syncthreads();

        const uint32_t kfb = sb + KOFF(j & 1) + kfoff;
        const uint32_t vfb = sb + VOFF + vfoff;
        const int kbase = j * 128;

        // S = Q @ K^T with index-validity mask (nonzero only in last tile)
        float sfr[16][4];
#pragma unroll
        for (int ntp = 0; ntp < 8; ntp++) {
            float c0[4] = {0.f, 0.f, 0.f, 0.f};
            float c1[4] = {0.f, 0.f, 0.f, 0.f};
#pragma unroll
            for (int ks = 0; ks < 8; ks++) {
                uint32_t f0, f1, f2, f3;
                ldsm_x4(f0, f1, f2, f3, kfb + (uint32_t)(ntp * (16 * ASTR * 2) + ks * 32));
                mma16816(c0, qa[ks][0], qa[ks][1], qa[ks][2], qa[ks][3], f0, f1);
                mma16816(c1, qa[ks][0], qa[ks][1], qa[ks][2], qa[ks][3], f2, f3);
            }
            const int k0 = kbase + 2 * ntp * 8 + 2 * tg;
            const int k1 = kbase + (2 * ntp + 1) * 8 + 2 * tg;
            float a00 = (k0 < nv)     ? 0.f : -1e30f;
            float a01 = (k0 + 1 < nv) ? 0.f : -1e30f;
            float a10 = (k1 < nv)     ? 0.f : -1e30f;
            float a11 = (k1 + 1 < nv) ? 0.f : -1e30f;
            sfr[2 * ntp][0] = c0[0] + a00; sfr[2 * ntp][1] = c0[1] + a01;
            sfr[2 * ntp][2] = c0[2] + a00; sfr[2 * ntp][3] = c0[3] + a01;
            sfr[2 * ntp + 1][0] = c1[0] + a10; sfr[2 * ntp + 1][1] = c1[1] + a11;
            sfr[2 * ntp + 1][2] = c1[2] + a10; sfr[2 * ntp + 1][3] = c1[3] + a11;
        }

        // online softmax
        float mx0 = -1e30f, mx1 = -1e30f;
#pragma unroll
        for (int nt = 0; nt < 16; nt++) {
            mx0 = fmaxf(mx0, fmaxf(sfr[nt][0], sfr[nt][1]));
            mx1 = fmaxf(mx1, fmaxf(sfr[nt][2], sfr[nt][3]));
        }
        mx0 = fmaxf(mx0, __shfl_xor_sync(0xffffffffu, mx0, 1));
        mx0 = fmaxf(mx0, __shfl_xor_sync(0xffffffffu, mx0, 2));
        mx1 = fmaxf(mx1, __shfl_xor_sync(0xffffffffu, mx1, 1));
        mx1 = fmaxf(mx1, __shfl_xor_sync(0xffffffffu, mx1, 2));
        float mn0 = fmaxf(mrun0, mx0), mn1 = fmaxf(mrun1, mx1);
        float al0 = ex2f(mrun0 - mn0), al1 = ex2f(mrun1 - mn1);
        mrun0 = mn0; mrun1 = mn1;

        float rs0 = 0.f, rs1 = 0.f;
        uint32_t pfr[16][2];
#pragma unroll
        for (int nt = 0; nt < 16; nt++) {
            float p0 = ex2f(sfr[nt][0] - mn0), p1 = ex2f(sfr[nt][1] - mn0);
            float p2 = ex2f(sfr[nt][2] - mn1), p3 = ex2f(sfr[nt][3] - mn1);
            rs0 += p0 + p1; rs1 += p2 + p3;
            pfr[nt][0] = pack_h2(p0, p1);
            pfr[nt][1] = pack_h2(p2, p3);
        }
        rs0 += __shfl_xor_sync(0xffffffffu, rs0, 1);
        rs0 += __shfl_xor_sync(0xffffffffu, rs0, 2);
        rs1 += __shfl_xor_sync(0xffffffffu, rs1, 1);
        rs1 += __shfl_xor_sync(0xffffffffu, rs1, 2);
        lsum0 = lsum0 * al0 + rs0;
        lsum1 = lsum1 * al1 + rs1;
#pragma unroll
        for (int nt = 0; nt < 16; nt++) {
            o[nt][0] *= al0; o[nt][1] *= al0; o[nt][2] *= al1; o[nt][3] *= al1;
        }

        // O += P @ V
#pragma unroll
        for (int ntp = 0; ntp < 8; ntp++) {
#pragma unroll
            for (int ks = 0; ks < 8; ks++) {
                uint32_t f0, f1, f2, f3;
                ldsm_x4_t(f0, f1, f2, f3, vfb + (uint32_t)(ks * (16 * ASTR * 2) + ntp * 32));
                mma16816(o[2 * ntp],     pfr[2 * ks][0], pfr[2 * ks][1],
                                          pfr[2 * ks + 1][0], pfr[2 * ks + 1][1], f0, f1);
                mma16816(o[2 * ntp + 1], pfr[2 * ks][0], pfr[2 * ks][1],
                                          pfr[2 * ks + 1][0], pfr[2 * ks + 1][1], f2, f3);
            }
        }
        __syncthreads();

        if (j < ntiles - 1) {   // refill single V buffer for next tile
            const __half* vg = Vb + (size_t)((j + 1) * 128) * CH;
            for (int i = tid; i < 2048; i += 128) {
                uint32_t r = i >> 4, ck = i & 15;
                cp16(sb + VOFF + (r * ASTR + ck * 8) * 2, vg + (size_t)r * CH + ck * 8);
            }
            asm volatile("cp.async.commit_group;\n");
        }
    }

    // ---- epilogue: normalize, residual, LayerNorm, coalesced store ----
    const float inv0 = 1.f / lsum0, inv1 = 1.f / lsum1;
    const int t0 = q0 + wm + g, t1 = t0 + 8;
    float yv[16][4];
    float s0 = 0.f, s1 = 0.f, sq0 = 0.f, sq1 = 0.f;
#pragma unroll
    for (int nt = 0; nt < 16; nt++) {
        int c0 = nt * 8 + 2 * tg;
        float x00 = x[((size_t)(b * CH + c0)) * NTOK + t0];
        float x01 = x[((size_t)(b * CH + c0 + 1)) * NTOK + t0];
        float x10 = x[((size_t)(b * CH + c0)) * NTOK + t1];
        float x11 = x[((size_t)(b * CH + c0 + 1)) * NTOK + t1];
        float y0 = o[nt][0] * inv0 + x00;
        float y1 = o[nt][1] * inv0 + x01;
        float y2 = o[nt][2] * inv1 + x10;
        float y3 = o[nt][3] * inv1 + x11;
        yv[nt][0] = y0; yv[nt][1] = y1; yv[nt][2] = y2; yv[nt][3] = y3;
        s0 += y0 + y1; s1 += y2 + y3;
        sq0 += y0 * y0 + y1 * y1; sq1 += y2 * y2 + y3 * y3;
    }
    s0 += __shfl_xor_sync(0xffffffffu, s0, 1);  s0 += __shfl_xor_sync(0xffffffffu, s0, 2);
    s1 += __shfl_xor_sync(0xffffffffu, s1, 1);  s1 += __shfl_xor_sync(0xffffffffu, s1, 2);
    sq0 += __shfl_xor_sync(0xffffffffu, sq0, 1); sq0 += __shfl_xor_sync(0xffffffffu, sq0, 2);
    sq1 += __shfl_xor_sync(0xffffffffu, sq1, 1); sq1 += __shfl_xor_sync(0xffffffffu, sq1, 2);
    const float mu0 = s0 * (1.f / 128.f), mu1 = s1 * (1.f / 128.f);
    const float rstd0 = rsqrtf(sq0 * (1.f / 128.f) - mu0 * mu0 + 1e-5f);
    const float rstd1 = rsqrtf(sq1 * (1.f / 128.f) - mu1 * mu1 + 1e-5f);

    const int tl0 = wm + g, tl1 = wm + g + 8;
#pragma unroll
    for (int nt = 0; nt < 16; nt++) {
        int c0 = nt * 8 + 2 * tg;
        float ga0 = __ldg(&gamma[c0]), ga1 = __ldg(&gamma[c0 + 1]);
        float be0 = __ldg(&beta[c0]),  be1 = __ldg(&beta[c0 + 1]);
        Ot[c0 * 68 + tl0]       = (yv[nt][0] - mu0) * rstd0 * ga0 + be0;
        Ot[(c0 + 1) * 68 + tl0] = (yv[nt][1] - mu0) * rstd0 * ga1 + be1;
        Ot[c0 * 68 + tl1]       = (yv[nt][2] - mu1) * rstd1 * ga0 + be0;
        Ot[(c0 + 1) * 68 + tl1] = (yv[nt][3] - mu1) * rstd1 * ga1 + be1;
    }
    __syncthreads();
    for (int i = tid; i < 128 * 16; i += 128) {
        int c = i >> 4, tq = i & 15;
        *(float4*)&out[((size_t)(b * CH + c)) * NTOK + q0 + tq * 4] =
            *(float4*)&Ot[c * 68 + tq * 4];
    }
}

// ============================================================================
extern "C" void kernel_launch(void* const* d_in, const int* in_sizes, int n_in,
                              void* d_out, int out_size)
{
    (void)in_sizes; (void)n_in; (void)out_size;
    const float* pf    = (const float*)d_in[0];
    const float* x     = (const float*)d_in[1];
    const float* Wq    = (const float*)d_in[2];
    const float* bq    = (const float*)d_in[3];
    const float* Wk    = (const float*)d_in[4];
    const float* bk    = (const float*)d_in[5];
    const float* Wv    = (const float*)d_in[6];
    const float* bv    = (const float*)d_in[7];
    const float* gamma = (const float*)d_in[8];
    const float* beta  = (const float*)d_in[9];
    const int*   mask  = (const int*)d_in[10];
    float* out = (float*)d_out;

    cudaFuncSetAttribute(proj_kernel, cudaFuncAttributeMaxDynamicSharedMemorySize, 72 * 1024);
    cudaFuncSetAttribute(attn_kernel, cudaFuncAttributeMaxDynamicSharedMemorySize, SMATT);

    dim3 g1(128, 3);
    proj_kernel<<<g1, 256, 71168>>>(pf, x, Wq, bq, Wk, bk, Wv, bv, mask);
    dim3 g2(64, 4);
    attn_kernel<<<g2, 128, SMATT>>>(x, gamma, beta, out);
}

// round 17
// speedup vs baseline: 1.0847x; 1.0073x over previous
#include <cuda_runtime.h>
#include <cuda_fp16.h>
#include <cstdint>

#define BATCH 4
#define CH    128
#define NTOK  4096
#define NPAD  4224   // NTOK + one pad tile
#define ASTR  136    // smem tile stride in halves

// ---- scratch (device globals; no runtime allocation) ----
__device__ __half g_Q [(size_t)BATCH * NTOK * CH];
__device__ __half g_Kc[(size_t)BATCH * NPAD * CH];   // compacted K (written by proj)
__device__ __half g_Vc[(size_t)BATCH * NPAD * CH];   // compacted V (written by proj)
__device__ int    g_scat[BATCH * NTOK];              // dest index for valid keys
__device__ int    g_nvalid[BATCH];
__device__ unsigned g_flag[BATCH];                   // scan-done flags (per batch)

// ---- PTX helpers ----
__device__ __forceinline__ void mma16816(float* c,
    uint32_t a0, uint32_t a1, uint32_t a2, uint32_t a3,
    uint32_t b0, uint32_t b1)
{
    asm volatile(
        "mma.sync.aligned.m16n8k16.row.col.f32.f16.f16.f32 "
        "{%0,%1,%2,%3},{%4,%5,%6,%7},{%8,%9},{%0,%1,%2,%3};\n"
        : "+f"(c[0]), "+f"(c[1]), "+f"(c[2]), "+f"(c[3])
        : "r"(a0), "r"(a1), "r"(a2), "r"(a3), "r"(b0), "r"(b1));
}
__device__ __forceinline__ void ldsm_x4(uint32_t& r0, uint32_t& r1, uint32_t& r2, uint32_t& r3, uint32_t a)
{
    asm volatile("ldmatrix.sync.aligned.m8n8.x4.shared.b16 {%0,%1,%2,%3}, [%4];\n"
                 : "=r"(r0), "=r"(r1), "=r"(r2), "=r"(r3) : "r"(a));
}
__device__ __forceinline__ void ldsm_x4_t(uint32_t& r0, uint32_t& r1, uint32_t& r2, uint32_t& r3, uint32_t a)
{
    asm volatile("ldmatrix.sync.aligned.m8n8.x4.trans.shared.b16 {%0,%1,%2,%3}, [%4];\n"
                 : "=r"(r0), "=r"(r1), "=r"(r2), "=r"(r3) : "r"(a));
}
__device__ __forceinline__ float ex2f(float x)
{ float r; asm("ex2.approx.f32 %0, %1;" : "=f"(r) : "f"(x)); return r; }
__device__ __forceinline__ uint32_t pack_h2(float lo, float hi)
{ __half2 h = __floats2half2_rn(lo, hi); return *reinterpret_cast<uint32_t*>(&h); }
__device__ __forceinline__ void cp16(uint32_t d, const void* s)
{ asm volatile("cp.async.cg.shared.global [%0], [%1], 16;\n" :: "r"(d), "l"(s)); }

// ============================================================================
// Kernel 1: QKV projections with INLINE mask scan.
// grid = (128, 3).  CTAs (y==0, x&31==0) scan batch x>>5 first, set g_flag.
// A tile stored [ch][token] (conflict-free vectorized fill); A-fragments via
// transposing ldmatrix (V-path pattern).  K/V rows scatter via g_scat.
// ============================================================================
__global__ __launch_bounds__(256, 1) void proj_kernel(
    const float* __restrict__ pf, const float* __restrict__ x,
    const float* __restrict__ Wq, const float* __restrict__ bq,
    const float* __restrict__ Wk, const float* __restrict__ bk,
    const float* __restrict__ Wv, const float* __restrict__ bv,
    const int* __restrict__ mask)
{
    extern __shared__ char sm[];
    __half* As  = (__half*)sm;                        // [ch][token], ASTR stride
    __half* Ws  = (__half*)(sm + 128 * ASTR * 2);
    float*  bia = (float*)(sm + 2 * 128 * ASTR * 2);
    const uint32_t sb = (uint32_t)__cvta_generic_to_shared(sm);

    const int tid = threadIdx.x;
    const int p   = blockIdx.y;
    const int t   = blockIdx.x;
    const int b   = t >> 5;
    const int n0  = (t & 31) * 128;
    const int lane = tid & 31, warp = tid >> 5;

    // ---- inline scan (4 designated CTAs, one per batch) ----
    if (p == 0 && (t & 31) == 0) {
        __shared__ int ws[9];
        const int base = b * NTOK + tid * 16;
        int4 mv[4];
#pragma unroll
        for (int q = 0; q < 4; q++) mv[q] = *(const int4*)(mask + base + q * 4);
        int m[16]; int c = 0;
#pragma unroll
        for (int q = 0; q < 4; q++) {
            m[q * 4 + 0] = (mv[q].x > 0);
            m[q * 4 + 1] = (mv[q].y > 0);
            m[q * 4 + 2] = (mv[q].z > 0);
            m[q * 4 + 3] = (mv[q].w > 0);
        }
#pragma unroll
        for (int k = 0; k < 16; k++) c += m[k];
        int pre = c;
#pragma unroll
        for (int d = 1; d < 32; d <<= 1) {
            int n = __shfl_up_sync(0xffffffffu, pre, d);
            if (lane >= d) pre += n;
        }
        if (lane == 31) ws[warp] = pre;
        __syncthreads();
        if (tid == 0) {
            int s = 0;
#pragma unroll
            for (int w = 0; w < 8; w++) { int tv = ws[w]; ws[w] = s; s += tv; }
            ws[8] = s;
            g_nvalid[b] = s;
        }
        __syncthreads();
        int off = ws[warp] + pre - c;
#pragma unroll
        for (int k = 0; k < 16; k++) { if (m[k]) g_scat[base + k] = off++; }

        const int nv = ws[8];
        const int padEnd = ((nv + 127) >> 7) << 7;
        const uint4 z = make_uint4(0, 0, 0, 0);
        for (int i = nv * 16 + tid; i < padEnd * 16; i += 256) {
            *(uint4*)(g_Kc + (size_t)b * NPAD * CH + (size_t)i * 8) = z;
            *(uint4*)(g_Vc + (size_t)b * NPAD * CH + (size_t)i * 8) = z;
        }
        __syncthreads();
        __threadfence();
        if (tid == 0) atomicExch(&g_flag[b], 1u);
        __syncthreads();
    }

    const float* src = (p == 0) ? pf : x;
    const float* W   = (p == 0) ? Wq : (p == 1 ? Wk : Wv);
    const float* bv_ = (p == 0) ? bq : (p == 1 ? bk : bv);
    const float oscale = (p == 0) ? (1.4426950408889634f / 11.313708498984761f) : 1.0f;

    // A fill: [ch][token] layout — float4 coalesced loads, contiguous 8B stores
    for (int i = tid; i < 32 * 128; i += 256) {
        int c = i >> 5, t4 = (i & 31) * 4;
        float4 v = *(const float4*)(src + ((size_t)(b * CH + c)) * NTOK + n0 + t4);
        uint2 pk;
        pk.x = pack_h2(v.x, v.y);
        pk.y = pack_h2(v.z, v.w);
        *(uint2*)&As[c * ASTR + t4] = pk;
    }
    for (int i = tid; i < 128 * 128; i += 256) {
        int o = i >> 7, k = i & 127;
        Ws[o * ASTR + k] = __float2half(W[o * CH + k]);
    }
    if (tid < 128) bia[tid] = bv_[tid];
    __syncthreads();

    const int g = lane >> 2, tg = lane & 3;
    const int quad = lane >> 3, wi = lane & 7;
    const int wm = warp * 16;

    // A fragments via transposing ldmatrix from [ch][token] storage.
    // Rows addressed = channel (k-dim), col bytes = token offset (wm).
    // Output perm: a0=f0, a1=f2, a2=f1, a3=f3.
    const uint32_t afoff = (uint32_t)((((quad & 1) * 8 + wi) * ASTR) * 2 + (quad >> 1) * 16 + wm * 2);
    uint32_t qa[8][4];
#pragma unroll
    for (int ks = 0; ks < 8; ks++) {
        uint32_t f0, f1, f2, f3;
        ldsm_x4_t(f0, f1, f2, f3, sb + afoff + (uint32_t)(ks * 16 * ASTR * 2));
        qa[ks][0] = f0; qa[ks][1] = f2; qa[ks][2] = f1; qa[ks][3] = f3;
    }

    // K/V CTAs: wait for this batch's scan before touching g_scat
    if (p != 0) {
        if (tid == 0) {
            while (atomicAdd(&g_flag[b], 0u) == 0u) __nanosleep(100);
        }
        __syncthreads();
    }

    // destination rows for this thread's two output rows
    const int gi0 = b * NTOK + n0 + wm + g;
    const int gi1 = gi0 + 8;
    size_t row0, row1;
    bool st0 = true, st1 = true;
    __half* dst;
    if (p == 0) {
        dst = g_Q;
        row0 = (size_t)gi0 * CH;
        row1 = (size_t)gi1 * CH;
    } else {
        dst = (p == 1) ? g_Kc : g_Vc;
        st0 = (mask[gi0] > 0);
        st1 = (mask[gi1] > 0);
        row0 = st0 ? ((size_t)b * NPAD + g_scat[gi0]) * CH : 0;
        row1 = st1 ? ((size_t)b * NPAD + g_scat[gi1]) * CH : 0;
    }

#pragma unroll
    for (int nt = 0; nt < 16; nt++) {
        float acc[4] = {0.f, 0.f, 0.f, 0.f};
#pragma unroll
        for (int ks = 0; ks < 8; ks++) {
            const __half* kb = &Ws[(nt * 8 + g) * ASTR + ks * 16 + 2 * tg];
            uint32_t b0 = *(const uint32_t*)kb;
            uint32_t b1 = *(const uint32_t*)(kb + 8);
            mma16816(acc, qa[ks][0], qa[ks][1], qa[ks][2], qa[ks][3], b0, b1);
        }
        int col = nt * 8 + 2 * tg;
        float bb0 = bia[col], bb1 = bia[col + 1];
        if (st0)
            *(__half2*)&dst[row0 + col] =
                __floats2half2_rn((acc[0] + bb0) * oscale, (acc[1] + bb1) * oscale);
        if (st1)
            *(__half2*)&dst[row1 + col] =
                __floats2half2_rn((acc[2] + bb0) * oscale, (acc[3] + bb1) * oscale);
    }
}

// ============================================================================
// Kernel 2: flash attention over compacted keys + residual + LayerNorm.
// grid=(64 qtiles, 4 batch), 128 threads (4 warps x 16 queries), 2 CTAs/SM.
// smem: K0 0 | K1 34816 | V 69632   (104448 B)
// ============================================================================
#define KOFF(i) ((i) * 34816)
#define VOFF    69632
#define SMATT   104448

__global__ __launch_bounds__(128, 2) void attn_kernel(
    const float* __restrict__ x,
    const float* __restrict__ gamma, const float* __restrict__ beta,
    float* __restrict__ out)
{
    extern __shared__ char sm[];
    const uint32_t sb = (uint32_t)__cvta_generic_to_shared(sm);
    float* Ot = (float*)sm;   // epilogue staging [128 ch][68], overlaps K0

    const int tid  = threadIdx.x;
    const int lane = tid & 31, warp = tid >> 5;
    const int g = lane >> 2, tg = lane & 3;
    const int quad = lane >> 3, wi = lane & 7;
    const int wm = warp * 16;
    const int b  = blockIdx.y;
    const int q0 = blockIdx.x * 64;

    const int nv = g_nvalid[b];
    const int ntiles = (nv + 127) >> 7;

    const uint32_t kfoff = (uint32_t)((((quad >> 1) * 8 + wi) * ASTR + (quad & 1) * 8) * 2);
    const uint32_t vfoff = (uint32_t)(((quad & 1) * 8 + wi) * ASTR * 2 + (quad >> 1) * 16);

    const __half* Kb = g_Kc + (size_t)b * NPAD * CH;
    const __half* Vb = g_Vc + (size_t)b * NPAD * CH;

    // prologue: prefetch K0 then V0 as separate commit groups
    {
        for (int i = tid; i < 2048; i += 128) {
            uint32_t r = i >> 4, ck = i & 15;
            cp16(sb + KOFF(0) + (r * ASTR + ck * 8) * 2, Kb + (size_t)r * CH + ck * 8);
        }
        asm volatile("cp.async.commit_group;\n");
        for (int i = tid; i < 2048; i += 128) {
            uint32_t r = i >> 4, ck = i & 15;
            cp16(sb + VOFF + (r * ASTR + ck * 8) * 2, Vb + (size_t)r * CH + ck * 8);
        }
        asm volatile("cp.async.commit_group;\n");
    }

    // resident Q fragments (pre-scaled by log2e/sqrt(C) in proj)
    uint32_t qa[8][4];
    {
        const __half* qp = g_Q + (size_t)(b * NTOK + q0 + wm + g) * CH;
#pragma unroll
        for (int ks = 0; ks < 8; ks++) {
            qa[ks][0] = *(const uint32_t*)(qp + ks * 16 + 2 * tg);
            qa[ks][1] = *(const uint32_t*)(qp + 8 * CH + ks * 16 + 2 * tg);
            qa[ks][2] = *(const uint32_t*)(qp + ks * 16 + 2 * tg + 8);
            qa[ks][3] = *(const uint32_t*)(qp + 8 * CH + ks * 16 + 2 * tg + 8);
        }
    }

    float o[16][4];
#pragma unroll
    for (int nt = 0; nt < 16; nt++) { o[nt][0] = o[nt][1] = o[nt][2] = o[nt][3] = 0.f; }
    float mrun0 = -1e30f, mrun1 = -1e30f, lsum0 = 0.f, lsum1 = 0.f;

    for (int j = 0; j < ntiles; j++) {
        if (j < ntiles - 1) {
            const int jn = j + 1;
            const uint32_t kb = sb + KOFF(jn & 1);
            const __half* kg = Kb + (size_t)(jn * 128) * CH;
            for (int i = tid; i < 2048; i += 128) {
                uint32_t r = i >> 4, ck = i & 15;
                cp16(kb + (r * ASTR + ck * 8) * 2, kg + (size_t)r * CH + ck * 8);
            }
            asm volatile("cp.async.commit_group;\n");
            asm volatile("cp.async.wait_group 1;\n" ::: "memory");
        } else {
            asm volatile("cp.async.wait_group 0;\n" ::: "memory");
        }
        __syncthreads();

        const uint32_t kfb = sb + KOFF(j & 1) + kfoff;
        const uint32_t vfb = sb + VOFF + vfoff;
        const int kbase = j * 128;

        // S = Q @ K^T with index-validity mask (nonzero only in last tile)
        float sfr[16][4];
#pragma unroll
        for (int ntp = 0; ntp < 8; ntp++) {
            float c0[4] = {0.f, 0.f, 0.f, 0.f};
            float c1[4] = {0.f, 0.f, 0.f, 0.f};
#pragma unroll
            for (int ks = 0; ks < 8; ks++) {
                uint32_t f0, f1, f2, f3;
                ldsm_x4(f0, f1, f2, f3, kfb + (uint32_t)(ntp * (16 * ASTR * 2) + ks * 32));
                mma16816(c0, qa[ks][0], qa[ks][1], qa[ks][2], qa[ks][3], f0, f1);
                mma16816(c1, qa[ks][0], qa[ks][1], qa[ks][2], qa[ks][3], f2, f3);
            }
            const int k0 = kbase + 2 * ntp * 8 + 2 * tg;
            const int k1 = kbase + (2 * ntp + 1) * 8 + 2 * tg;
            float a00 = (k0 < nv)     ? 0.f : -1e30f;
            float a01 = (k0 + 1 < nv) ? 0.f : -1e30f;
            float a10 = (k1 < nv)     ? 0.f : -1e30f;
            float a11 = (k1 + 1 < nv) ? 0.f : -1e30f;
            sfr[2 * ntp][0] = c0[0] + a00; sfr[2 * ntp][1] = c0[1] + a01;
            sfr[2 * ntp][2] = c0[2] + a00; sfr[2 * ntp][3] = c0[3] + a01;
            sfr[2 * ntp + 1][0] = c1[0] + a10; sfr[2 * ntp + 1][1] = c1[1] + a11;
            sfr[2 * ntp + 1][2] = c1[2] + a10; sfr[2 * ntp + 1][3] = c1[3] + a11;
        }

        // online softmax
        float mx0 = -1e30f, mx1 = -1e30f;
#pragma unroll
        for (int nt = 0; nt < 16; nt++) {
            mx0 = fmaxf(mx0, fmaxf(sfr[nt][0], sfr[nt][1]));
            mx1 = fmaxf(mx1, fmaxf(sfr[nt][2], sfr[nt][3]));
        }
        mx0 = fmaxf(mx0, __shfl_xor_sync(0xffffffffu, mx0, 1));
        mx0 = fmaxf(mx0, __shfl_xor_sync(0xffffffffu, mx0, 2));
        mx1 = fmaxf(mx1, __shfl_xor_sync(0xffffffffu, mx1, 1));
        mx1 = fmaxf(mx1, __shfl_xor_sync(0xffffffffu, mx1, 2));
        float mn0 = fmaxf(mrun0, mx0), mn1 = fmaxf(mrun1, mx1);
        float al0 = ex2f(mrun0 - mn0), al1 = ex2f(mrun1 - mn1);
        mrun0 = mn0; mrun1 = mn1;

        float rs0 = 0.f, rs1 = 0.f;
        uint32_t pfr[16][2];
#pragma unroll
        for (int nt = 0; nt < 16; nt++) {
            float p0 = ex2f(sfr[nt][0] - mn0), p1 = ex2f(sfr[nt][1] - mn0);
            float p2 = ex2f(sfr[nt][2] - mn1), p3 = ex2f(sfr[nt][3] - mn1);
            rs0 += p0 + p1; rs1 += p2 + p3;
            pfr[nt][0] = pack_h2(p0, p1);
            pfr[nt][1] = pack_h2(p2, p3);
        }
        rs0 += __shfl_xor_sync(0xffffffffu, rs0, 1);
        rs0 += __shfl_xor_sync(0xffffffffu, rs0, 2);
        rs1 += __shfl_xor_sync(0xffffffffu, rs1, 1);
        rs1 += __shfl_xor_sync(0xffffffffu, rs1, 2);
        lsum0 = lsum0 * al0 + rs0;
        lsum1 = lsum1 * al1 + rs1;
#pragma unroll
        for (int nt = 0; nt < 16; nt++) {
            o[nt][0] *= al0; o[nt][1] *= al0; o[nt][2] *= al1; o[nt][3] *= al1;
        }

        // O += P @ V
#pragma unroll
        for (int ntp = 0; ntp < 8; ntp++) {
#pragma unroll
            for (int ks = 0; ks < 8; ks++) {
                uint32_t f0, f1, f2, f3;
                ldsm_x4_t(f0, f1, f2, f3, vfb + (uint32_t)(ks * (16 * ASTR * 2) + ntp * 32));
                mma16816(o[2 * ntp],     pfr[2 * ks][0], pfr[2 * ks][1],
                                          pfr[2 * ks + 1][0], pfr[2 * ks + 1][1], f0, f1);
                mma16816(o[2 * ntp + 1], pfr[2 * ks][0], pfr[2 * ks][1],
                                          pfr[2 * ks + 1][0], pfr[2 * ks + 1][1], f2, f3);
            }
        }
        __syncthreads();

        if (j < ntiles - 1) {   // refill single V buffer for next tile
            const __half* vg = Vb + (size_t)((j + 1) * 128) * CH;
            for (int i = tid; i < 2048; i += 128) {
                uint32_t r = i >> 4, ck = i & 15;
                cp16(sb + VOFF + (r * ASTR + ck * 8) * 2, vg + (size_t)r * CH + ck * 8);
            }
            asm volatile("cp.async.commit_group;\n");
        }
    }

    // ---- epilogue: normalize, residual, LayerNorm, coalesced store ----
    const float inv0 = 1.f / lsum0, inv1 = 1.f / lsum1;
    const int t0 = q0 + wm + g, t1 = t0 + 8;
    float yv[16][4];
    float s0 = 0.f, s1 = 0.f, sq0 = 0.f, sq1 = 0.f;
#pragma unroll
    for (int nt = 0; nt < 16; nt++) {
        int c0 = nt * 8 + 2 * tg;
        float x00 = x[((size_t)(b * CH + c0)) * NTOK + t0];
        float x01 = x[((size_t)(b * CH + c0 + 1)) * NTOK + t0];
        float x10 = x[((size_t)(b * CH + c0)) * NTOK + t1];
        float x11 = x[((size_t)(b * CH + c0 + 1)) * NTOK + t1];
        float y0 = o[nt][0] * inv0 + x00;
        float y1 = o[nt][1] * inv0 + x01;
        float y2 = o[nt][2] * inv1 + x10;
        float y3 = o[nt][3] * inv1 + x11;
        yv[nt][0] = y0; yv[nt][1] = y1; yv[nt][2] = y2; yv[nt][3] = y3;
        s0 += y0 + y1; s1 += y2 + y3;
        sq0 += y0 * y0 + y1 * y1; sq1 += y2 * y2 + y3 * y3;
    }
    s0 += __shfl_xor_sync(0xffffffffu, s0, 1);  s0 += __shfl_xor_sync(0xffffffffu, s0, 2);
    s1 += __shfl_xor_sync(0xffffffffu, s1, 1);  s1 += __shfl_xor_sync(0xffffffffu, s1, 2);
    sq0 += __shfl_xor_sync(0xffffffffu, sq0, 1); sq0 += __shfl_xor_sync(0xffffffffu, sq0, 2);
    sq1 += __shfl_xor_sync(0xffffffffu, sq1, 1); sq1 += __shfl_xor_sync(0xffffffffu, sq1, 2);
    const float mu0 = s0 * (1.f / 128.f), mu1 = s1 * (1.f / 128.f);
    const float rstd0 = rsqrtf(sq0 * (1.f / 128.f) - mu0 * mu0 + 1e-5f);
    const float rstd1 = rsqrtf(sq1 * (1.f / 128.f) - mu1 * mu1 + 1e-5f);

    const int tl0 = wm + g, tl1 = wm + g + 8;
#pragma unroll
    for (int nt = 0; nt < 16; nt++) {
        int c0 = nt * 8 + 2 * tg;
        float ga0 = __ldg(&gamma[c0]), ga1 = __ldg(&gamma[c0 + 1]);
        float be0 = __ldg(&beta[c0]),  be1 = __ldg(&beta[c0 + 1]);
        Ot[c0 * 68 + tl0]       = (yv[nt][0] - mu0) * rstd0 * ga0 + be0;
        Ot[(c0 + 1) * 68 + tl0] = (yv[nt][1] - mu0) * rstd0 * ga1 + be1;
        Ot[c0 * 68 + tl1]       = (yv[nt][2] - mu1) * rstd1 * ga0 + be0;
        Ot[(c0 + 1) * 68 + tl1] = (yv[nt][3] - mu1) * rstd1 * ga1 + be1;
    }
    __syncthreads();
    for (int i = tid; i < 128 * 16; i += 128) {
        int c = i >> 4, tq = i & 15;
        *(float4*)&out[((size_t)(b * CH + c)) * NTOK + q0 + tq * 4] =
            *(float4*)&Ot[c * 68 + tq * 4];
    }
}

// ============================================================================
extern "C" void kernel_launch(void* const* d_in, const int* in_sizes, int n_in,
                              void* d_out, int out_size)
{
    (void)in_sizes; (void)n_in; (void)out_size;
    const float* pf    = (const float*)d_in[0];
    const float* x     = (const float*)d_in[1];
    const float* Wq    = (const float*)d_in[2];
    const float* bq    = (const float*)d_in[3];
    const float* Wk    = (const float*)d_in[4];
    const float* bk    = (const float*)d_in[5];
    const float* Wv    = (const float*)d_in[6];
    const float* bv    = (const float*)d_in[7];
    const float* gamma = (const float*)d_in[8];
    const float* beta  = (const float*)d_in[9];
    const int*   mask  = (const int*)d_in[10];
    float* out = (float*)d_out;

    cudaFuncSetAttribute(proj_kernel, cudaFuncAttributeMaxDynamicSharedMemorySize, 72 * 1024);
    cudaFuncSetAttribute(attn_kernel, cudaFuncAttributeMaxDynamicSharedMemorySize, SMATT);

    dim3 g1(128, 3);
    proj_kernel<<<g1, 256, 71168>>>(pf, x, Wq, bq, Wk, bk, Wv, bv, mask);
    dim3 g2(64, 4);
    attn_kernel<<<g2, 128, SMATT>>>(x, gamma, beta, out);
}